// round 8
// baseline (speedup 1.0000x reference)
#include <cuda_runtime.h>
#include <math.h>

// Problem constants (fixed by the reference setup)
#define N_USER 60000
#define N_ITEM 40000
#define NN     (N_USER + N_ITEM)   // 100000 nodes
#define D      64
#define EMAX   800000
#define EHALF  (EMAX / 2)
#define NB_SCAN ((NN + 1023) / 1024)   // 98 blocks

// persistent-kernel geometry: 4 blocks/SM x 148 SMs (GB300 has 152 -> headroom)
#define NBLK   592
#define NTHR   256
#define NWARPS (NBLK * (NTHR / 32))    // 4736

// ---- static device scratch (no allocations allowed) ----
__device__ float  g_embA[NN * D];
__device__ float  g_embB[NN * D];
__device__ float  g_light[NN * D];
__device__ float  g_rnorm[NN];    // reciprocal norms
__device__ float  g_rowsum[NN];   // reciprocal L1 rowsums (1 if rowsum<=0)
__device__ float4 g_edge[EMAX];   // {col(bits), cos, mem, aval}
__device__ int2   g_cr[EHALF];    // user-side CSR slots: {col, reverse slot}
__device__ int    g_rowptr[NN + 1];
__device__ int    g_deg[NN];
__device__ int    g_bsum[128];
__device__ int    g_bar_count;
__device__ volatile unsigned g_bar_gen;

// ---------------- software grid barrier (all NBLK blocks resident) ----------------

__device__ __forceinline__ void grid_barrier() {
    __threadfence();          // release this thread's writes device-wide
    __syncthreads();
    if (threadIdx.x == 0) {
        unsigned gen = g_bar_gen;
        if (atomicAdd(&g_bar_count, 1) == NBLK - 1) {
            g_bar_count = 0;
            __threadfence();
            g_bar_gen = gen + 1;
        } else {
            while (g_bar_gen == gen) __nanosleep(64);
        }
        __threadfence();      // acquire
    }
    __syncthreads();
}

// ---------------- CSR build ----------------

__global__ void k_hist(const int* __restrict__ src, int E) {
    for (int e = blockIdx.x * blockDim.x + threadIdx.x; e < E;
         e += gridDim.x * blockDim.x)
        atomicAdd(&g_deg[src[e]], 1);
}

__global__ void k_scanA() {
    __shared__ int wsum[32];
    int i = blockIdx.x * 1024 + threadIdx.x;
    int lane = threadIdx.x & 31, wid = threadIdx.x >> 5;
    int v = (i < NN) ? g_deg[i] : 0;
    int x = v;
    #pragma unroll
    for (int o = 1; o < 32; o <<= 1) {
        int y = __shfl_up_sync(0xffffffffu, x, o);
        if (lane >= o) x += y;
    }
    if (lane == 31) wsum[wid] = x;
    __syncthreads();
    if (wid == 0) {
        int s = wsum[lane];
        #pragma unroll
        for (int o = 1; o < 32; o <<= 1) {
            int y = __shfl_up_sync(0xffffffffu, s, o);
            if (lane >= o) s += y;
        }
        wsum[lane] = s;
    }
    __syncthreads();
    int woff = (wid > 0) ? wsum[wid - 1] : 0;
    int incl = x + woff;
    if (i < NN) g_rowptr[i] = incl - v;  // exclusive, local to block
    if (threadIdx.x == 1023) g_bsum[blockIdx.x] = incl;
}

__global__ void k_scanB(int nb) {
    int i = threadIdx.x;
    int v = (i < nb) ? g_bsum[i] : 0;
    int x = v;
    #pragma unroll
    for (int o = 1; o < 32; o <<= 1) {
        int y = __shfl_up_sync(0xffffffffu, x, o);
        if ((i & 31) >= o) x += y;
    }
    __shared__ int ws[4];
    if ((i & 31) == 31) ws[i >> 5] = x;
    __syncthreads();
    int off = 0;
    for (int w = 0; w < (i >> 5); w++) off += ws[w];
    if (i < nb) g_bsum[i] = x - v + off;  // exclusive
}

__global__ void k_scanC(int E) {
    int i = blockIdx.x * 1024 + threadIdx.x;
    if (i < NN) {
        g_rowptr[i] += g_bsum[blockIdx.x];
        g_deg[i] = 0;  // reset as scatter cursor
    }
    if (i == 0) g_rowptr[NN] = E;
}

// scatter BOTH directions of each undirected edge; record reverse-slot mapping.
__global__ void k_scatter(const int* __restrict__ src, const float* __restrict__ adj,
                          int EH) {
    for (int e = blockIdx.x * blockDim.x + threadIdx.x; e < EH;
         e += gridDim.x * blockDim.x) {
        int u = src[e];
        int i = src[e + EH];
        float a = adj[e];
        int pos1 = g_rowptr[u] + atomicAdd(&g_deg[u], 1);
        int pos2 = g_rowptr[i] + atomicAdd(&g_deg[i], 1);
        g_edge[pos1] = make_float4(__int_as_float(i), 0.f, a, a);
        g_edge[pos2] = make_float4(__int_as_float(u), 0.f, a, a);
        g_cr[pos1]   = make_int2(i, pos2);   // user rows occupy slots [0, EH)
    }
}

// ---------------- fused persistent kernel: init + 3 propagation layers ----------------
// Phase bodies are the verified R7 bodies. Cross-block-produced data is read
// with __ldcg (L1 bypass) because L1 is NOT flushed between in-kernel phases.

__global__ __launch_bounds__(NTHR, 4) void k_layers(const float* __restrict__ W,
                                                    const float* __restrict__ B,
                                                    const float* __restrict__ ue,
                                                    const float* __restrict__ ie) {
    int wgid = (blockIdx.x * NTHR + threadIdx.x) >> 5;
    int lane = threadIdx.x & 31;
    int g = lane >> 3, sl = lane & 7;

    // ---- phase 0: init embeddings + light + layer-0 rnorm ----
    for (int row = wgid; row < NN; row += NWARPS) {
        const float* srcp = (row < N_USER) ? (ue + row * D) : (ie + (row - N_USER) * D);
        float2 v = *(const float2*)(srcp + lane * 2);
        *(float2*)(g_embA + row * D + lane * 2)  = v;
        *(float2*)(g_light + row * D + lane * 2) = v;
        float s = v.x * v.x + v.y * v.y;
        #pragma unroll
        for (int o = 16; o; o >>= 1) s += __shfl_xor_sync(0xffffffffu, s, o);
        if (lane == 0) g_rnorm[row] = (s > 1e-24f) ? rsqrtf(s) : 0.f;
    }
    grid_barrier();

    float w0 = W[0], w1 = W[1], bb = B[0];

    for (int l = 0; l < 3; l++) {
        const float* embin = (l & 1) ? g_embB : g_embA;
        float* embout      = (l & 1) ? g_embA : g_embB;
        bool last = (l == 2);

        // ---- phase 1: cos over USER rows (cos symmetric; scatter to reverse slot) ----
        for (int row = wgid; row < N_USER; row += NWARPS) {
            const float* rp = embin + row * D + sl * 4;
            float4 e0 = *(const float4*)(rp);
            float4 e1 = *(const float4*)(rp + 32);
            float rn_r = __ldcg(&g_rnorm[row]);

            int beg = g_rowptr[row], end = g_rowptr[row + 1];
            int nit = (end - beg + 3) >> 2;

            int pos = beg + g;
            bool actn = pos < end;
            int2 crn = actn ? g_cr[pos] : make_int2(0, 0);

            float rs = 0.f;
            for (int it = 0; it < nit; it++) {
                bool act = actn;
                int2 cr = crn;
                int curpos = pos;
                pos += 4;
                actn = pos < end;
                if (actn) crn = g_cr[pos];

                float p = 0.f;
                float rn_c = 0.f;
                if (act) {
                    const float4* cp = (const float4*)(embin + cr.x * D + sl * 4);
                    float4 d0 = __ldcg(cp);
                    float4 d1 = __ldcg(cp + 8);   // +32 floats
                    rn_c = __ldcg(&g_rnorm[cr.x]);
                    p = e0.x * d0.x + e0.y * d0.y + e0.z * d0.z + e0.w * d0.w
                      + e1.x * d1.x + e1.y * d1.y + e1.z * d1.z + e1.w * d1.w;
                }
                p += __shfl_xor_sync(0xffffffffu, p, 1);
                p += __shfl_xor_sync(0xffffffffu, p, 2);
                p += __shfl_xor_sync(0xffffffffu, p, 4);
                float cs = p * rn_r * rn_c;
                if (act && sl == 0) {
                    ((float*)(g_edge + curpos))[1] = cs;   // user-side slot
                    ((float*)(g_edge + cr.y))[1]   = cs;   // item-side (reverse) slot
                }
                rs += fabsf(cs);
            }
            rs += __shfl_xor_sync(0xffffffffu, rs, 8);
            rs += __shfl_xor_sync(0xffffffffu, rs, 16);
            if (lane == 0) g_rowsum[row] = (rs > 0.f) ? 1.f / rs : 1.f;
        }
        grid_barrier();

        // ---- phase 2: item-row reciprocal L1 rowsums (scalar reads of cos) ----
        for (int row = N_USER + wgid; row < NN; row += NWARPS) {
            int beg = g_rowptr[row], end = g_rowptr[row + 1];
            float rs = 0.f;
            for (int pos = beg + lane; pos < end; pos += 32)
                rs += fabsf(__ldcg(((const float*)(g_edge + pos)) + 1));
            #pragma unroll
            for (int o = 16; o; o >>= 1) rs += __shfl_xor_sync(0xffffffffu, rs, o);
            if (lane == 0) g_rowsum[row] = (rs > 0.f) ? 1.f / rs : 1.f;
        }
        grid_barrier();

        // ---- phase 3: coef -> prune -> mem EMA -> SpMM (+ light, + next rnorm) ----
        for (int row = wgid; row < NN; row += NWARPS) {
            float invr = __ldcg(&g_rowsum[row]);
            int beg = g_rowptr[row], end = g_rowptr[row + 1];
            int nit = (end - beg + 3) >> 2;

            int pos = beg + g;
            bool actn = pos < end;
            float4 en = actn ? __ldcg(&g_edge[pos]) : make_float4(0, 0, 0, 0);

            float a0 = 0.f, a1 = 0.f, a2 = 0.f, a3 = 0.f;
            float a4 = 0.f, a5 = 0.f, a6 = 0.f, a7 = 0.f;
            for (int it = 0; it < nit; it++) {
                bool act = actn;
                float4 er = en;
                int curpos = pos;
                pos += 4;
                actn = pos < end;
                if (actn) en = __ldcg(&g_edge[pos]);

                if (act) {
                    int c = __float_as_int(er.x);
                    float cs = er.y;
                    float c1 = cs * invr;
                    float c2 = cs * __ldcg(&g_rowsum[c]);
                    float z = w0 * c1 + w1 * c2 + bb;      // sigmoid(z)>0.5 <=> z>0
                    float coef = (z > 0.f) ? c1 : 0.f;
                    float m = 0.5f * (er.z + coef);
                    if (!last && sl == 0) ((float*)(g_edge + curpos))[2] = m;
                    float gv = m * er.w;
                    const float4* cp = (const float4*)(embin + c * D + sl * 4);
                    float4 d0 = __ldcg(cp);
                    float4 d1 = __ldcg(cp + 8);
                    a0 += gv * d0.x; a1 += gv * d0.y; a2 += gv * d0.z; a3 += gv * d0.w;
                    a4 += gv * d1.x; a5 += gv * d1.y; a6 += gv * d1.z; a7 += gv * d1.w;
                }
            }
            #pragma unroll
            for (int o = 8; o <= 16; o <<= 1) {
                a0 += __shfl_xor_sync(0xffffffffu, a0, o);
                a1 += __shfl_xor_sync(0xffffffffu, a1, o);
                a2 += __shfl_xor_sync(0xffffffffu, a2, o);
                a3 += __shfl_xor_sync(0xffffffffu, a3, o);
                a4 += __shfl_xor_sync(0xffffffffu, a4, o);
                a5 += __shfl_xor_sync(0xffffffffu, a5, o);
                a6 += __shfl_xor_sync(0xffffffffu, a6, o);
                a7 += __shfl_xor_sync(0xffffffffu, a7, o);
            }
            if (g == 0) {
                float* lp = g_light + row * D + sl * 4;
                float4 l0 = *(float4*)(lp);
                float4 l1 = *(float4*)(lp + 32);
                l0.x += a0; l0.y += a1; l0.z += a2; l0.w += a3;
                l1.x += a4; l1.y += a5; l1.z += a6; l1.w += a7;
                *(float4*)(lp)      = l0;
                *(float4*)(lp + 32) = l1;
            }
            if (!last) {
                float ss = a0 * a0 + a1 * a1 + a2 * a2 + a3 * a3
                         + a4 * a4 + a5 * a5 + a6 * a6 + a7 * a7;
                ss += __shfl_xor_sync(0xffffffffu, ss, 1);
                ss += __shfl_xor_sync(0xffffffffu, ss, 2);
                ss += __shfl_xor_sync(0xffffffffu, ss, 4);
                if (g == 0) {
                    float* op = embout + row * D + sl * 4;
                    *(float4*)(op)      = make_float4(a0, a1, a2, a3);
                    *(float4*)(op + 32) = make_float4(a4, a5, a6, a7);
                    if (sl == 0) g_rnorm[row] = (ss > 1e-24f) ? rsqrtf(ss) : 0.f;
                }
            }
        }
        if (!last) grid_barrier();
    }
}

// ---------------- final: fused gather + sigmoid GEMM ----------------

__global__ void k_gemm(const int* __restrict__ users, const int* __restrict__ items,
                       float* __restrict__ out, int Bu, int Bi) {
    __shared__ float As[64][65];
    __shared__ float Bs[64][65];
    int tx = threadIdx.x, ty = threadIdx.y;       // 16x16
    int t = ty * 16 + tx;
    int rowBase = blockIdx.y * 64, colBase = blockIdx.x * 64;
    #pragma unroll
    for (int i = 0; i < 4; i++) {
        int j = t + i * 256;       // float4 slot 0..1023
        int r = j >> 4;
        int kq = (j & 15) * 4;
        float4 a = make_float4(0, 0, 0, 0);
        if (rowBase + r < Bu) {
            int u = users[rowBase + r];
            float4 v = *(const float4*)(g_light + u * D + kq);
            a = make_float4(0.25f * v.x, 0.25f * v.y, 0.25f * v.z, 0.25f * v.w);
        }
        As[r][kq] = a.x; As[r][kq + 1] = a.y; As[r][kq + 2] = a.z; As[r][kq + 3] = a.w;
        float4 b = make_float4(0, 0, 0, 0);
        if (colBase + r < Bi) {
            int itm = items[colBase + r];
            float4 v = *(const float4*)(g_light + (N_USER + itm) * D + kq);
            b = make_float4(0.25f * v.x, 0.25f * v.y, 0.25f * v.z, 0.25f * v.w);
        }
        Bs[r][kq] = b.x; Bs[r][kq + 1] = b.y; Bs[r][kq + 2] = b.z; Bs[r][kq + 3] = b.w;
    }
    __syncthreads();
    float acc[4][4] = {};
    #pragma unroll
    for (int k = 0; k < 64; k++) {
        float a0 = As[ty * 4 + 0][k], a1 = As[ty * 4 + 1][k];
        float a2 = As[ty * 4 + 2][k], a3 = As[ty * 4 + 3][k];
        float b0 = Bs[tx * 4 + 0][k], b1 = Bs[tx * 4 + 1][k];
        float b2 = Bs[tx * 4 + 2][k], b3 = Bs[tx * 4 + 3][k];
        acc[0][0] += a0 * b0; acc[0][1] += a0 * b1; acc[0][2] += a0 * b2; acc[0][3] += a0 * b3;
        acc[1][0] += a1 * b0; acc[1][1] += a1 * b1; acc[1][2] += a1 * b2; acc[1][3] += a1 * b3;
        acc[2][0] += a2 * b0; acc[2][1] += a2 * b1; acc[2][2] += a2 * b2; acc[2][3] += a2 * b3;
        acc[3][0] += a3 * b0; acc[3][1] += a3 * b1; acc[3][2] += a3 * b2; acc[3][3] += a3 * b3;
    }
    #pragma unroll
    for (int i = 0; i < 4; i++)
        #pragma unroll
        for (int j = 0; j < 4; j++) {
            int r = rowBase + ty * 4 + i;
            int c = colBase + tx * 4 + j;
            if (r < Bu && c < Bi)
                out[r * Bi + c] = 1.f / (1.f + __expf(-acc[i][j]));
        }
}

// ---------------- launch ----------------

extern "C" void kernel_launch(void* const* d_in, const int* in_sizes, int n_in,
                              void* d_out, int out_size) {
    const int*   users    = (const int*)d_in[0];
    const int*   items    = (const int*)d_in[1];
    const float* user_emb = (const float*)d_in[2];
    const float* item_emb = (const float*)d_in[3];
    const float* W_prune  = (const float*)d_in[4];
    const float* b_prune  = (const float*)d_in[5];
    const int*   src      = (const int*)d_in[6];
    // d_in[7] = dst (mirrors src), d_in[8] = rev_perm (unused)
    const float* adj_vals = (const float*)d_in[9];

    int Bu = in_sizes[0];
    int Bi = in_sizes[1];
    int E  = in_sizes[6];
    int EH = E / 2;

    float* out = (float*)d_out;

    // zero degree counters
    void* degp = nullptr;
    cudaGetSymbolAddress(&degp, g_deg);
    cudaMemsetAsync(degp, 0, NN * sizeof(int));

    // CSR build
    k_hist<<<(E + 1023) / 1024, 1024>>>(src, E);
    k_scanA<<<NB_SCAN, 1024>>>();
    k_scanB<<<1, 128>>>(NB_SCAN);
    k_scanC<<<NB_SCAN, 1024>>>(E);
    k_scatter<<<(EH + 1023) / 1024, 1024>>>(src, adj_vals, EH);

    // fused persistent kernel: init + 3 layers with software grid barriers
    k_layers<<<NBLK, NTHR>>>(W_prune, b_prune, user_emb, item_emb);

    // fused gather + sigmoid GEMM
    dim3 gblk(16, 16);
    dim3 ggrd((Bi + 63) / 64, (Bu + 63) / 64);
    k_gemm<<<ggrd, gblk>>>(users, items, out, Bu, Bi);
}

// round 9
// speedup vs baseline: 1.0076x; 1.0076x over previous
#include <cuda_runtime.h>
#include <math.h>

// Problem constants (fixed by the reference setup)
#define N_USER 60000
#define N_ITEM 40000
#define NN     (N_USER + N_ITEM)   // 100000 nodes
#define D      64
#define EMAX   800000
#define EHALF  (EMAX / 2)
#define NB_SCAN ((NN + 1023) / 1024)   // 98 blocks

// persistent-kernel geometry: 4 blocks/SM x 148 SMs (GB300 has 152 -> headroom)
#define NBLK   592
#define NTHR   256
#define NWARPS (NBLK * (NTHR / 32))    // 4736

// ---- static device scratch (no allocations allowed) ----
__device__ float  g_embA[NN * D];
__device__ float  g_embB[NN * D];
__device__ float  g_light[NN * D];
__device__ float  g_rnorm[NN];    // reciprocal norms
__device__ float  g_rowsum[NN];   // reciprocal L1 rowsums (1 if rowsum<=0)
__device__ float4 g_edge[EMAX];   // {col(bits), cos, mem, aval}
__device__ int2   g_cr[EHALF];    // user-side CSR slots: {col, reverse slot}
__device__ int    g_rowptr[NN + 1];
__device__ int    g_deg[NN];
__device__ int    g_bsum[128];
__device__ int    g_bar_count;
__device__ volatile unsigned g_bar_gen;

// ---------------- software grid barrier (all NBLK blocks resident) ----------------
// __threadfence() is gpu-scope (>= cluster) so ptxas emits CCTL.IVALL: it both
// releases this block's writes AND invalidates L1D, making post-barrier normal
// (.ca) loads coherent with all pre-barrier writes from any SM.

__device__ __forceinline__ void grid_barrier() {
    __threadfence();          // release + L1D invalidate (CCTL.IVALL)
    __syncthreads();
    if (threadIdx.x == 0) {
        unsigned gen = g_bar_gen;
        if (atomicAdd(&g_bar_count, 1) == NBLK - 1) {
            g_bar_count = 0;
            __threadfence();
            g_bar_gen = gen + 1;
        } else {
            while (g_bar_gen == gen) __nanosleep(64);
        }
        __threadfence();      // acquire (+ IVALL again for thread 0)
    }
    __syncthreads();
}

// ---------------- CSR build ----------------

__global__ void k_hist(const int* __restrict__ src, int E) {
    for (int e = blockIdx.x * blockDim.x + threadIdx.x; e < E;
         e += gridDim.x * blockDim.x)
        atomicAdd(&g_deg[src[e]], 1);
}

__global__ void k_scanA() {
    __shared__ int wsum[32];
    int i = blockIdx.x * 1024 + threadIdx.x;
    int lane = threadIdx.x & 31, wid = threadIdx.x >> 5;
    int v = (i < NN) ? g_deg[i] : 0;
    int x = v;
    #pragma unroll
    for (int o = 1; o < 32; o <<= 1) {
        int y = __shfl_up_sync(0xffffffffu, x, o);
        if (lane >= o) x += y;
    }
    if (lane == 31) wsum[wid] = x;
    __syncthreads();
    if (wid == 0) {
        int s = wsum[lane];
        #pragma unroll
        for (int o = 1; o < 32; o <<= 1) {
            int y = __shfl_up_sync(0xffffffffu, s, o);
            if (lane >= o) s += y;
        }
        wsum[lane] = s;
    }
    __syncthreads();
    int woff = (wid > 0) ? wsum[wid - 1] : 0;
    int incl = x + woff;
    if (i < NN) g_rowptr[i] = incl - v;  // exclusive, local to block
    if (threadIdx.x == 1023) g_bsum[blockIdx.x] = incl;
}

__global__ void k_scanB(int nb) {
    int i = threadIdx.x;
    int v = (i < nb) ? g_bsum[i] : 0;
    int x = v;
    #pragma unroll
    for (int o = 1; o < 32; o <<= 1) {
        int y = __shfl_up_sync(0xffffffffu, x, o);
        if ((i & 31) >= o) x += y;
    }
    __shared__ int ws[4];
    if ((i & 31) == 31) ws[i >> 5] = x;
    __syncthreads();
    int off = 0;
    for (int w = 0; w < (i >> 5); w++) off += ws[w];
    if (i < nb) g_bsum[i] = x - v + off;  // exclusive
}

__global__ void k_scanC(int E) {
    int i = blockIdx.x * 1024 + threadIdx.x;
    if (i < NN) {
        g_rowptr[i] += g_bsum[blockIdx.x];
        g_deg[i] = 0;  // reset as scatter cursor
    }
    if (i == 0) g_rowptr[NN] = E;
}

// scatter BOTH directions of each undirected edge; record reverse-slot mapping.
__global__ void k_scatter(const int* __restrict__ src, const float* __restrict__ adj,
                          int EH) {
    for (int e = blockIdx.x * blockDim.x + threadIdx.x; e < EH;
         e += gridDim.x * blockDim.x) {
        int u = src[e];
        int i = src[e + EH];
        float a = adj[e];
        int pos1 = g_rowptr[u] + atomicAdd(&g_deg[u], 1);
        int pos2 = g_rowptr[i] + atomicAdd(&g_deg[i], 1);
        g_edge[pos1] = make_float4(__int_as_float(i), 0.f, a, a);
        g_edge[pos2] = make_float4(__int_as_float(u), 0.f, a, a);
        g_cr[pos1]   = make_int2(i, pos2);   // user rows occupy slots [0, EH)
    }
}

// ---------------- fused persistent kernel: init + 3 propagation layers ----------------
// Phase bodies are the verified R7 bodies with NORMAL (L1-cached) loads.
// Coherence across phases is provided by grid_barrier's CCTL.IVALL.

__global__ __launch_bounds__(NTHR, 4) void k_layers(const float* __restrict__ W,
                                                    const float* __restrict__ B,
                                                    const float* __restrict__ ue,
                                                    const float* __restrict__ ie) {
    int wgid = (blockIdx.x * NTHR + threadIdx.x) >> 5;
    int lane = threadIdx.x & 31;
    int g = lane >> 3, sl = lane & 7;

    // ---- phase 0: init embeddings + light + layer-0 rnorm ----
    for (int row = wgid; row < NN; row += NWARPS) {
        const float* srcp = (row < N_USER) ? (ue + row * D) : (ie + (row - N_USER) * D);
        float2 v = *(const float2*)(srcp + lane * 2);
        *(float2*)(g_embA + row * D + lane * 2)  = v;
        *(float2*)(g_light + row * D + lane * 2) = v;
        float s = v.x * v.x + v.y * v.y;
        #pragma unroll
        for (int o = 16; o; o >>= 1) s += __shfl_xor_sync(0xffffffffu, s, o);
        if (lane == 0) g_rnorm[row] = (s > 1e-24f) ? rsqrtf(s) : 0.f;
    }
    grid_barrier();

    float w0 = W[0], w1 = W[1], bb = B[0];

    for (int l = 0; l < 3; l++) {
        const float* __restrict__ embin = (l & 1) ? g_embB : g_embA;
        float* embout                   = (l & 1) ? g_embA : g_embB;
        bool last = (l == 2);

        // ---- phase 1: cos over USER rows (cos symmetric; scatter to reverse slot) ----
        for (int row = wgid; row < N_USER; row += NWARPS) {
            const float* rp = embin + row * D + sl * 4;
            float4 e0 = *(const float4*)(rp);
            float4 e1 = *(const float4*)(rp + 32);
            float rn_r = g_rnorm[row];

            int beg = g_rowptr[row], end = g_rowptr[row + 1];
            int nit = (end - beg + 3) >> 2;

            int pos = beg + g;
            bool actn = pos < end;
            int2 crn = actn ? g_cr[pos] : make_int2(0, 0);

            float rs = 0.f;
            for (int it = 0; it < nit; it++) {
                bool act = actn;
                int2 cr = crn;
                int curpos = pos;
                pos += 4;
                actn = pos < end;
                if (actn) crn = g_cr[pos];

                float p = 0.f;
                float rn_c = 0.f;
                if (act) {
                    const float* cp = embin + cr.x * D + sl * 4;
                    float4 d0 = *(const float4*)(cp);
                    float4 d1 = *(const float4*)(cp + 32);
                    rn_c = g_rnorm[cr.x];
                    p = e0.x * d0.x + e0.y * d0.y + e0.z * d0.z + e0.w * d0.w
                      + e1.x * d1.x + e1.y * d1.y + e1.z * d1.z + e1.w * d1.w;
                }
                p += __shfl_xor_sync(0xffffffffu, p, 1);
                p += __shfl_xor_sync(0xffffffffu, p, 2);
                p += __shfl_xor_sync(0xffffffffu, p, 4);
                float cs = p * rn_r * rn_c;
                if (act && sl == 0) {
                    ((float*)(g_edge + curpos))[1] = cs;   // user-side slot
                    ((float*)(g_edge + cr.y))[1]   = cs;   // item-side (reverse) slot
                }
                rs += fabsf(cs);
            }
            rs += __shfl_xor_sync(0xffffffffu, rs, 8);
            rs += __shfl_xor_sync(0xffffffffu, rs, 16);
            if (lane == 0) g_rowsum[row] = (rs > 0.f) ? 1.f / rs : 1.f;
        }
        grid_barrier();

        // ---- phase 2: item-row reciprocal L1 rowsums (scalar reads of cos) ----
        for (int row = N_USER + wgid; row < NN; row += NWARPS) {
            int beg = g_rowptr[row], end = g_rowptr[row + 1];
            float rs = 0.f;
            for (int pos = beg + lane; pos < end; pos += 32)
                rs += fabsf(((const float*)(g_edge + pos))[1]);
            #pragma unroll
            for (int o = 16; o; o >>= 1) rs += __shfl_xor_sync(0xffffffffu, rs, o);
            if (lane == 0) g_rowsum[row] = (rs > 0.f) ? 1.f / rs : 1.f;
        }
        grid_barrier();

        // ---- phase 3: coef -> prune -> mem EMA -> SpMM (+ light, + next rnorm) ----
        for (int row = wgid; row < NN; row += NWARPS) {
            float invr = g_rowsum[row];
            int beg = g_rowptr[row], end = g_rowptr[row + 1];
            int nit = (end - beg + 3) >> 2;

            int pos = beg + g;
            bool actn = pos < end;
            float4 en = actn ? g_edge[pos] : make_float4(0, 0, 0, 0);

            float a0 = 0.f, a1 = 0.f, a2 = 0.f, a3 = 0.f;
            float a4 = 0.f, a5 = 0.f, a6 = 0.f, a7 = 0.f;
            for (int it = 0; it < nit; it++) {
                bool act = actn;
                float4 er = en;
                int curpos = pos;
                pos += 4;
                actn = pos < end;
                if (actn) en = g_edge[pos];

                if (act) {
                    int c = __float_as_int(er.x);
                    float cs = er.y;
                    float c1 = cs * invr;
                    float c2 = cs * g_rowsum[c];
                    float z = w0 * c1 + w1 * c2 + bb;      // sigmoid(z)>0.5 <=> z>0
                    float coef = (z > 0.f) ? c1 : 0.f;
                    float m = 0.5f * (er.z + coef);
                    if (!last && sl == 0) ((float*)(g_edge + curpos))[2] = m;
                    float gv = m * er.w;
                    const float* cp = embin + c * D + sl * 4;
                    float4 d0 = *(const float4*)(cp);
                    float4 d1 = *(const float4*)(cp + 32);
                    a0 += gv * d0.x; a1 += gv * d0.y; a2 += gv * d0.z; a3 += gv * d0.w;
                    a4 += gv * d1.x; a5 += gv * d1.y; a6 += gv * d1.z; a7 += gv * d1.w;
                }
            }
            #pragma unroll
            for (int o = 8; o <= 16; o <<= 1) {
                a0 += __shfl_xor_sync(0xffffffffu, a0, o);
                a1 += __shfl_xor_sync(0xffffffffu, a1, o);
                a2 += __shfl_xor_sync(0xffffffffu, a2, o);
                a3 += __shfl_xor_sync(0xffffffffu, a3, o);
                a4 += __shfl_xor_sync(0xffffffffu, a4, o);
                a5 += __shfl_xor_sync(0xffffffffu, a5, o);
                a6 += __shfl_xor_sync(0xffffffffu, a6, o);
                a7 += __shfl_xor_sync(0xffffffffu, a7, o);
            }
            if (g == 0) {
                float* lp = g_light + row * D + sl * 4;
                float4 l0 = *(float4*)(lp);
                float4 l1 = *(float4*)(lp + 32);
                l0.x += a0; l0.y += a1; l0.z += a2; l0.w += a3;
                l1.x += a4; l1.y += a5; l1.z += a6; l1.w += a7;
                *(float4*)(lp)      = l0;
                *(float4*)(lp + 32) = l1;
            }
            if (!last) {
                float ss = a0 * a0 + a1 * a1 + a2 * a2 + a3 * a3
                         + a4 * a4 + a5 * a5 + a6 * a6 + a7 * a7;
                ss += __shfl_xor_sync(0xffffffffu, ss, 1);
                ss += __shfl_xor_sync(0xffffffffu, ss, 2);
                ss += __shfl_xor_sync(0xffffffffu, ss, 4);
                if (g == 0) {
                    float* op = embout + row * D + sl * 4;
                    *(float4*)(op)      = make_float4(a0, a1, a2, a3);
                    *(float4*)(op + 32) = make_float4(a4, a5, a6, a7);
                    if (sl == 0) g_rnorm[row] = (ss > 1e-24f) ? rsqrtf(ss) : 0.f;
                }
            }
        }
        if (!last) grid_barrier();
    }
}

// ---------------- final: fused gather + sigmoid GEMM ----------------

__global__ void k_gemm(const int* __restrict__ users, const int* __restrict__ items,
                       float* __restrict__ out, int Bu, int Bi) {
    __shared__ float As[64][65];
    __shared__ float Bs[64][65];
    int tx = threadIdx.x, ty = threadIdx.y;       // 16x16
    int t = ty * 16 + tx;
    int rowBase = blockIdx.y * 64, colBase = blockIdx.x * 64;
    #pragma unroll
    for (int i = 0; i < 4; i++) {
        int j = t + i * 256;       // float4 slot 0..1023
        int r = j >> 4;
        int kq = (j & 15) * 4;
        float4 a = make_float4(0, 0, 0, 0);
        if (rowBase + r < Bu) {
            int u = users[rowBase + r];
            float4 v = *(const float4*)(g_light + u * D + kq);
            a = make_float4(0.25f * v.x, 0.25f * v.y, 0.25f * v.z, 0.25f * v.w);
        }
        As[r][kq] = a.x; As[r][kq + 1] = a.y; As[r][kq + 2] = a.z; As[r][kq + 3] = a.w;
        float4 b = make_float4(0, 0, 0, 0);
        if (colBase + r < Bi) {
            int itm = items[colBase + r];
            float4 v = *(const float4*)(g_light + (N_USER + itm) * D + kq);
            b = make_float4(0.25f * v.x, 0.25f * v.y, 0.25f * v.z, 0.25f * v.w);
        }
        Bs[r][kq] = b.x; Bs[r][kq + 1] = b.y; Bs[r][kq + 2] = b.z; Bs[r][kq + 3] = b.w;
    }
    __syncthreads();
    float acc[4][4] = {};
    #pragma unroll
    for (int k = 0; k < 64; k++) {
        float a0 = As[ty * 4 + 0][k], a1 = As[ty * 4 + 1][k];
        float a2 = As[ty * 4 + 2][k], a3 = As[ty * 4 + 3][k];
        float b0 = Bs[tx * 4 + 0][k], b1 = Bs[tx * 4 + 1][k];
        float b2 = Bs[tx * 4 + 2][k], b3 = Bs[tx * 4 + 3][k];
        acc[0][0] += a0 * b0; acc[0][1] += a0 * b1; acc[0][2] += a0 * b2; acc[0][3] += a0 * b3;
        acc[1][0] += a1 * b0; acc[1][1] += a1 * b1; acc[1][2] += a1 * b2; acc[1][3] += a1 * b3;
        acc[2][0] += a2 * b0; acc[2][1] += a2 * b1; acc[2][2] += a2 * b2; acc[2][3] += a2 * b3;
        acc[3][0] += a3 * b0; acc[3][1] += a3 * b1; acc[3][2] += a3 * b2; acc[3][3] += a3 * b3;
    }
    #pragma unroll
    for (int i = 0; i < 4; i++)
        #pragma unroll
        for (int j = 0; j < 4; j++) {
            int r = rowBase + ty * 4 + i;
            int c = colBase + tx * 4 + j;
            if (r < Bu && c < Bi)
                out[r * Bi + c] = 1.f / (1.f + __expf(-acc[i][j]));
        }
}

// ---------------- launch ----------------

extern "C" void kernel_launch(void* const* d_in, const int* in_sizes, int n_in,
                              void* d_out, int out_size) {
    const int*   users    = (const int*)d_in[0];
    const int*   items    = (const int*)d_in[1];
    const float* user_emb = (const float*)d_in[2];
    const float* item_emb = (const float*)d_in[3];
    const float* W_prune  = (const float*)d_in[4];
    const float* b_prune  = (const float*)d_in[5];
    const int*   src      = (const int*)d_in[6];
    // d_in[7] = dst (mirrors src), d_in[8] = rev_perm (unused)
    const float* adj_vals = (const float*)d_in[9];

    int Bu = in_sizes[0];
    int Bi = in_sizes[1];
    int E  = in_sizes[6];
    int EH = E / 2;

    float* out = (float*)d_out;

    // zero degree counters
    void* degp = nullptr;
    cudaGetSymbolAddress(&degp, g_deg);
    cudaMemsetAsync(degp, 0, NN * sizeof(int));

    // CSR build
    k_hist<<<(E + 1023) / 1024, 1024>>>(src, E);
    k_scanA<<<NB_SCAN, 1024>>>();
    k_scanB<<<1, 128>>>(NB_SCAN);
    k_scanC<<<NB_SCAN, 1024>>>(E);
    k_scatter<<<(EH + 1023) / 1024, 1024>>>(src, adj_vals, EH);

    // fused persistent kernel: init + 3 layers with software grid barriers
    k_layers<<<NBLK, NTHR>>>(W_prune, b_prune, user_emb, item_emb);

    // fused gather + sigmoid GEMM
    dim3 gblk(16, 16);
    dim3 ggrd((Bi + 63) / 64, (Bu + 63) / 64);
    k_gemm<<<ggrd, gblk>>>(users, items, out, Bu, Bi);
}

// round 10
// speedup vs baseline: 1.5224x; 1.5110x over previous
#include <cuda_runtime.h>
#include <math.h>

// Problem constants (fixed by the reference setup)
#define N_USER 60000
#define N_ITEM 40000
#define NN     (N_USER + N_ITEM)   // 100000 nodes
#define D      64
#define EMAX   800000
#define EHALF  (EMAX / 2)
#define NB_SCAN ((NN + 1023) / 1024)   // 98 blocks

// ---- static device scratch (no allocations allowed) ----
__device__ float  g_embA[NN * D];   // emb0 -> overwritten by emb2 (layer-1 output)
__device__ float  g_embB[NN * D];   // emb1 (layer-0 output), preserved
__device__ float  g_rnorm[NN];      // reciprocal norms
__device__ float  g_rowsum[NN];     // reciprocal L1 rowsums (1 if rowsum<=0)
__device__ float4 g_edge[EMAX];     // {col(bits), cos, mem, aval}
__device__ int2   g_cr[EHALF];      // user-side CSR slots: {col, reverse slot}
__device__ int    g_rowptr[NN + 1];
__device__ int    g_deg[NN];
__device__ int    g_bsum[128];
__device__ float  g_U[2048 * D];    // 0.25*(emb0+..+emb3) at sampled user rows
__device__ float  g_I[2048 * D];    // same for items

// ---------------- CSR build ----------------

__global__ void k_hist(const int* __restrict__ src, int E) {
    for (int e = blockIdx.x * blockDim.x + threadIdx.x; e < E;
         e += gridDim.x * blockDim.x)
        atomicAdd(&g_deg[src[e]], 1);
}

__global__ void k_scanA() {
    __shared__ int wsum[32];
    int i = blockIdx.x * 1024 + threadIdx.x;
    int lane = threadIdx.x & 31, wid = threadIdx.x >> 5;
    int v = (i < NN) ? g_deg[i] : 0;
    int x = v;
    #pragma unroll
    for (int o = 1; o < 32; o <<= 1) {
        int y = __shfl_up_sync(0xffffffffu, x, o);
        if (lane >= o) x += y;
    }
    if (lane == 31) wsum[wid] = x;
    __syncthreads();
    if (wid == 0) {
        int s = wsum[lane];
        #pragma unroll
        for (int o = 1; o < 32; o <<= 1) {
            int y = __shfl_up_sync(0xffffffffu, s, o);
            if (lane >= o) s += y;
        }
        wsum[lane] = s;
    }
    __syncthreads();
    int woff = (wid > 0) ? wsum[wid - 1] : 0;
    int incl = x + woff;
    if (i < NN) g_rowptr[i] = incl - v;  // exclusive, local to block
    if (threadIdx.x == 1023) g_bsum[blockIdx.x] = incl;
}

// adds cross-block offsets (inline exclusive prefix over <=128 block sums)
__global__ void k_scanC(int E) {
    __shared__ int ssum[128];
    int t = threadIdx.x;
    if (t < 128) ssum[t] = (t < blockIdx.x) ? g_bsum[t] : 0;
    __syncthreads();
    // tree-reduce 128 values
    if (t < 64) ssum[t] += ssum[t + 64];
    __syncthreads();
    if (t < 32) {
        int s = ssum[t] + ssum[t + 32];
        #pragma unroll
        for (int o = 16; o; o >>= 1) s += __shfl_down_sync(0xffffffffu, s, o);
        if (t == 0) ssum[0] = s;
    }
    __syncthreads();
    int off = ssum[0];
    int i = blockIdx.x * 1024 + t;
    if (i < NN) {
        g_rowptr[i] += off;
        g_deg[i] = 0;  // reset as scatter cursor
    }
    if (i == 0) g_rowptr[NN] = E;
}

// scatter BOTH directions of each undirected edge; record reverse-slot mapping.
__global__ void k_scatter(const int* __restrict__ src, const float* __restrict__ adj,
                          int EH) {
    for (int e = blockIdx.x * blockDim.x + threadIdx.x; e < EH;
         e += gridDim.x * blockDim.x) {
        int u = src[e];
        int i = src[e + EH];
        float a = adj[e];
        int pos1 = g_rowptr[u] + atomicAdd(&g_deg[u], 1);
        int pos2 = g_rowptr[i] + atomicAdd(&g_deg[i], 1);
        g_edge[pos1] = make_float4(__int_as_float(i), 0.f, a, a);
        g_edge[pos2] = make_float4(__int_as_float(u), 0.f, a, a);
        g_cr[pos1]   = make_int2(i, pos2);   // user rows occupy slots [0, EH)
    }
}

// ---------------- init embeddings + layer-0 rnorm (fused; no light) ----------------

__global__ void k_init(const float* __restrict__ ue, const float* __restrict__ ie) {
    int row = blockIdx.x * (blockDim.x >> 5) + (threadIdx.x >> 5);
    if (row >= NN) return;
    int lane = threadIdx.x & 31;
    const float* srcp = (row < N_USER) ? (ue + row * D) : (ie + (row - N_USER) * D);
    float2 v = *(const float2*)(srcp + lane * 2);
    *(float2*)(g_embA + row * D + lane * 2) = v;
    float s = v.x * v.x + v.y * v.y;
    #pragma unroll
    for (int o = 16; o; o >>= 1) s += __shfl_xor_sync(0xffffffffu, s, o);
    if (lane == 0) g_rnorm[row] = (s > 1e-24f) ? rsqrtf(s) : 0.f;
}

// ---------------- per-layer edge passes (verified R7 bodies) ----------------
// k_cos: USER rows only (cos symmetric; scatter to reverse slot too).
// Warp per row; 4 edge-groups of 8 lanes; lane sl covers dims [4sl,4sl+4) and
// [32+4sl,+4) so each LDG.128 covers exactly one 128B line of the row.

__global__ __launch_bounds__(256) void k_cos(int cur) {
    const float* __restrict__ emb = cur ? g_embB : g_embA;
    int row = blockIdx.x * 8 + (threadIdx.x >> 5);
    if (row >= N_USER) return;
    int lane = threadIdx.x & 31;
    int g = lane >> 3, sl = lane & 7;

    const float* rp = emb + row * D + sl * 4;
    float4 e0 = *(const float4*)(rp);
    float4 e1 = *(const float4*)(rp + 32);
    float rn_r = g_rnorm[row];

    int beg = g_rowptr[row], end = g_rowptr[row + 1];
    int nit = (end - beg + 3) >> 2;

    int pos = beg + g;
    bool actn = pos < end;
    int2 crn = actn ? g_cr[pos] : make_int2(0, 0);

    float rs = 0.f;
    for (int it = 0; it < nit; it++) {
        bool act = actn;
        int2 cr = crn;
        int curpos = pos;
        pos += 4;
        actn = pos < end;
        if (actn) crn = g_cr[pos];

        float p = 0.f;
        float rn_c = 0.f;
        if (act) {
            const float* cp = emb + cr.x * D + sl * 4;
            float4 d0 = *(const float4*)(cp);
            float4 d1 = *(const float4*)(cp + 32);
            rn_c = g_rnorm[cr.x];
            p = e0.x * d0.x + e0.y * d0.y + e0.z * d0.z + e0.w * d0.w
              + e1.x * d1.x + e1.y * d1.y + e1.z * d1.z + e1.w * d1.w;
        }
        p += __shfl_xor_sync(0xffffffffu, p, 1);
        p += __shfl_xor_sync(0xffffffffu, p, 2);
        p += __shfl_xor_sync(0xffffffffu, p, 4);
        float cs = p * rn_r * rn_c;
        if (act && sl == 0) {
            ((float*)(g_edge + curpos))[1] = cs;   // user-side slot
            ((float*)(g_edge + cr.y))[1]   = cs;   // item-side (reverse) slot
        }
        rs += fabsf(cs);
    }
    rs += __shfl_xor_sync(0xffffffffu, rs, 8);
    rs += __shfl_xor_sync(0xffffffffu, rs, 16);
    if (lane == 0) g_rowsum[row] = (rs > 0.f) ? 1.f / rs : 1.f;
}

// item-row reciprocal L1 rowsums from the already-written cos values
__global__ __launch_bounds__(256) void k_rowsum_it() {
    int row = N_USER + blockIdx.x * 8 + (threadIdx.x >> 5);
    if (row >= NN) return;
    int lane = threadIdx.x & 31;
    int beg = g_rowptr[row], end = g_rowptr[row + 1];
    float rs = 0.f;
    for (int pos = beg + lane; pos < end; pos += 32)
        rs += fabsf(((const float*)(g_edge + pos))[1]);
    #pragma unroll
    for (int o = 16; o; o >>= 1) rs += __shfl_xor_sync(0xffffffffu, rs, o);
    if (lane == 0) g_rowsum[row] = (rs > 0.f) ? 1.f / rs : 1.f;
}

// layers 0,1 only: coef -> prune -> mem EMA -> SpMM row accumulate (+ next rnorm)
__global__ __launch_bounds__(256) void k_spmm(int cur,
                                              const float* __restrict__ W,
                                              const float* __restrict__ B) {
    const float* __restrict__ embin = cur ? g_embB : g_embA;
    float* embout                   = cur ? g_embA : g_embB;
    int row = blockIdx.x * 8 + (threadIdx.x >> 5);
    if (row >= NN) return;
    int lane = threadIdx.x & 31;
    int g = lane >> 3, sl = lane & 7;

    float w0 = W[0], w1 = W[1], bb = B[0];
    float invr = g_rowsum[row];
    int beg = g_rowptr[row], end = g_rowptr[row + 1];
    int nit = (end - beg + 3) >> 2;

    int pos = beg + g;
    bool actn = pos < end;
    float4 en = actn ? g_edge[pos] : make_float4(0, 0, 0, 0);

    float a0 = 0.f, a1 = 0.f, a2 = 0.f, a3 = 0.f;
    float a4 = 0.f, a5 = 0.f, a6 = 0.f, a7 = 0.f;
    for (int it = 0; it < nit; it++) {
        bool act = actn;
        float4 er = en;
        int curpos = pos;
        pos += 4;
        actn = pos < end;
        if (actn) en = g_edge[pos];

        if (act) {
            int c = __float_as_int(er.x);
            float cs = er.y;
            float c1 = cs * invr;
            float c2 = cs * g_rowsum[c];           // cos symmetric
            float z = w0 * c1 + w1 * c2 + bb;      // sigmoid(z)>0.5 <=> z>0
            float coef = (z > 0.f) ? c1 : 0.f;
            float m = 0.5f * (er.z + coef);
            if (sl == 0) ((float*)(g_edge + curpos))[2] = m;
            float gv = m * er.w;
            const float* cp = embin + c * D + sl * 4;
            float4 d0 = *(const float4*)(cp);
            float4 d1 = *(const float4*)(cp + 32);
            a0 += gv * d0.x; a1 += gv * d0.y; a2 += gv * d0.z; a3 += gv * d0.w;
            a4 += gv * d1.x; a5 += gv * d1.y; a6 += gv * d1.z; a7 += gv * d1.w;
        }
    }
    #pragma unroll
    for (int o = 8; o <= 16; o <<= 1) {
        a0 += __shfl_xor_sync(0xffffffffu, a0, o);
        a1 += __shfl_xor_sync(0xffffffffu, a1, o);
        a2 += __shfl_xor_sync(0xffffffffu, a2, o);
        a3 += __shfl_xor_sync(0xffffffffu, a3, o);
        a4 += __shfl_xor_sync(0xffffffffu, a4, o);
        a5 += __shfl_xor_sync(0xffffffffu, a5, o);
        a6 += __shfl_xor_sync(0xffffffffu, a6, o);
        a7 += __shfl_xor_sync(0xffffffffu, a7, o);
    }
    float ss = a0 * a0 + a1 * a1 + a2 * a2 + a3 * a3
             + a4 * a4 + a5 * a5 + a6 * a6 + a7 * a7;
    ss += __shfl_xor_sync(0xffffffffu, ss, 1);
    ss += __shfl_xor_sync(0xffffffffu, ss, 2);
    ss += __shfl_xor_sync(0xffffffffu, ss, 4);
    if (g == 0) {
        float* op = embout + row * D + sl * 4;
        *(float4*)(op)      = make_float4(a0, a1, a2, a3);
        *(float4*)(op + 32) = make_float4(a4, a5, a6, a7);
        if (sl == 0) g_rnorm[row] = (ss > 1e-24f) ? rsqrtf(ss) : 0.f;
    }
}

// layer-2 SpMM restricted to the SAMPLED rows only, fused with the light mean:
// g_U/g_I = 0.25*(emb0(inputs) + emb1(embB) + emb2(embA) + emb3(computed here))
__global__ __launch_bounds__(256) void k_final(const int* __restrict__ users,
                                               const int* __restrict__ items,
                                               const float* __restrict__ ue,
                                               const float* __restrict__ ie,
                                               const float* __restrict__ W,
                                               const float* __restrict__ B,
                                               int Bu, int Bi) {
    int idx = blockIdx.x * 8 + (threadIdx.x >> 5);   // sample index
    if (idx >= Bu + Bi) return;
    int lane = threadIdx.x & 31;
    int g = lane >> 3, sl = lane & 7;

    bool isU = idx < Bu;
    int row = isU ? users[idx] : (N_USER + items[idx - Bu]);
    float* outp = isU ? (g_U + idx * D) : (g_I + (idx - Bu) * D);
    const float* e0p = isU ? (ue + row * D) : (ie + (row - N_USER) * D);

    // emb2 is in g_embA (layer-1 output, cur=1 -> embout = embA)
    const float* __restrict__ embin = g_embA;

    float w0 = W[0], w1 = W[1], bb = B[0];
    float invr = g_rowsum[row];
    int beg = g_rowptr[row], end = g_rowptr[row + 1];
    int nit = (end - beg + 3) >> 2;

    int pos = beg + g;
    bool actn = pos < end;
    float4 en = actn ? g_edge[pos] : make_float4(0, 0, 0, 0);

    float a0 = 0.f, a1 = 0.f, a2 = 0.f, a3 = 0.f;
    float a4 = 0.f, a5 = 0.f, a6 = 0.f, a7 = 0.f;
    for (int it = 0; it < nit; it++) {
        bool act = actn;
        float4 er = en;
        pos += 4;
        actn = pos < end;
        if (actn) en = g_edge[pos];

        if (act) {
            int c = __float_as_int(er.x);
            float cs = er.y;
            float c1 = cs * invr;
            float c2 = cs * g_rowsum[c];
            float z = w0 * c1 + w1 * c2 + bb;
            float coef = (z > 0.f) ? c1 : 0.f;
            float m = 0.5f * (er.z + coef);      // no mem writeback (last layer)
            float gv = m * er.w;
            const float* cp = embin + c * D + sl * 4;
            float4 d0 = *(const float4*)(cp);
            float4 d1 = *(const float4*)(cp + 32);
            a0 += gv * d0.x; a1 += gv * d0.y; a2 += gv * d0.z; a3 += gv * d0.w;
            a4 += gv * d1.x; a5 += gv * d1.y; a6 += gv * d1.z; a7 += gv * d1.w;
        }
    }
    #pragma unroll
    for (int o = 8; o <= 16; o <<= 1) {
        a0 += __shfl_xor_sync(0xffffffffu, a0, o);
        a1 += __shfl_xor_sync(0xffffffffu, a1, o);
        a2 += __shfl_xor_sync(0xffffffffu, a2, o);
        a3 += __shfl_xor_sync(0xffffffffu, a3, o);
        a4 += __shfl_xor_sync(0xffffffffu, a4, o);
        a5 += __shfl_xor_sync(0xffffffffu, a5, o);
        a6 += __shfl_xor_sync(0xffffffffu, a6, o);
        a7 += __shfl_xor_sync(0xffffffffu, a7, o);
    }
    if (g == 0) {
        // lane sl holds emb3 for dims [4sl,4sl+4) and [32+4sl,+4)
        float4 z0 = *(const float4*)(e0p + sl * 4);          // emb0 (inputs)
        float4 z1 = *(const float4*)(e0p + sl * 4 + 32);
        const float* b1 = g_embB + row * D + sl * 4;          // emb1
        float4 y0 = *(const float4*)(b1);
        float4 y1 = *(const float4*)(b1 + 32);
        const float* b2 = g_embA + row * D + sl * 4;          // emb2
        float4 x0 = *(const float4*)(b2);
        float4 x1 = *(const float4*)(b2 + 32);
        float4 r0 = make_float4(0.25f * (z0.x + y0.x + x0.x + a0),
                                0.25f * (z0.y + y0.y + x0.y + a1),
                                0.25f * (z0.z + y0.z + x0.z + a2),
                                0.25f * (z0.w + y0.w + x0.w + a3));
        float4 r1 = make_float4(0.25f * (z1.x + y1.x + x1.x + a4),
                                0.25f * (z1.y + y1.y + x1.y + a5),
                                0.25f * (z1.z + y1.z + x1.z + a6),
                                0.25f * (z1.w + y1.w + x1.w + a7));
        *(float4*)(outp + sl * 4)      = r0;
        *(float4*)(outp + sl * 4 + 32) = r1;
    }
}

// ---------------- final sigmoid GEMM (dense g_U x g_I^T) ----------------

__global__ void k_gemm(float* __restrict__ out, int Bu, int Bi) {
    __shared__ float As[64][65];
    __shared__ float Bs[64][65];
    int tx = threadIdx.x, ty = threadIdx.y;       // 16x16
    int t = ty * 16 + tx;
    int rowBase = blockIdx.y * 64, colBase = blockIdx.x * 64;
    #pragma unroll
    for (int i = 0; i < 4; i++) {
        int j = t + i * 256;       // float4 slot 0..1023
        int r = j >> 4;
        int kq = (j & 15) * 4;
        float4 a = (rowBase + r < Bu) ? *(const float4*)(g_U + (rowBase + r) * 64 + kq)
                                      : make_float4(0, 0, 0, 0);
        As[r][kq] = a.x; As[r][kq + 1] = a.y; As[r][kq + 2] = a.z; As[r][kq + 3] = a.w;
        float4 b = (colBase + r < Bi) ? *(const float4*)(g_I + (colBase + r) * 64 + kq)
                                      : make_float4(0, 0, 0, 0);
        Bs[r][kq] = b.x; Bs[r][kq + 1] = b.y; Bs[r][kq + 2] = b.z; Bs[r][kq + 3] = b.w;
    }
    __syncthreads();
    float acc[4][4] = {};
    #pragma unroll
    for (int k = 0; k < 64; k++) {
        float a0 = As[ty * 4 + 0][k], a1 = As[ty * 4 + 1][k];
        float a2 = As[ty * 4 + 2][k], a3 = As[ty * 4 + 3][k];
        float b0 = Bs[tx * 4 + 0][k], b1 = Bs[tx * 4 + 1][k];
        float b2 = Bs[tx * 4 + 2][k], b3 = Bs[tx * 4 + 3][k];
        acc[0][0] += a0 * b0; acc[0][1] += a0 * b1; acc[0][2] += a0 * b2; acc[0][3] += a0 * b3;
        acc[1][0] += a1 * b0; acc[1][1] += a1 * b1; acc[1][2] += a1 * b2; acc[1][3] += a1 * b3;
        acc[2][0] += a2 * b0; acc[2][1] += a2 * b1; acc[2][2] += a2 * b2; acc[2][3] += a2 * b3;
        acc[3][0] += a3 * b0; acc[3][1] += a3 * b1; acc[3][2] += a3 * b2; acc[3][3] += a3 * b3;
    }
    #pragma unroll
    for (int i = 0; i < 4; i++)
        #pragma unroll
        for (int j = 0; j < 4; j++) {
            int r = rowBase + ty * 4 + i;
            int c = colBase + tx * 4 + j;
            if (r < Bu && c < Bi)
                out[r * Bi + c] = 1.f / (1.f + __expf(-acc[i][j]));
        }
}

// ---------------- launch ----------------

extern "C" void kernel_launch(void* const* d_in, const int* in_sizes, int n_in,
                              void* d_out, int out_size) {
    const int*   users    = (const int*)d_in[0];
    const int*   items    = (const int*)d_in[1];
    const float* user_emb = (const float*)d_in[2];
    const float* item_emb = (const float*)d_in[3];
    const float* W_prune  = (const float*)d_in[4];
    const float* b_prune  = (const float*)d_in[5];
    const int*   src      = (const int*)d_in[6];
    // d_in[7] = dst (mirrors src), d_in[8] = rev_perm (unused)
    const float* adj_vals = (const float*)d_in[9];

    int Bu = in_sizes[0];
    int Bi = in_sizes[1];
    int E  = in_sizes[6];
    int EH = E / 2;

    float* out = (float*)d_out;

    // zero degree counters
    void* degp = nullptr;
    cudaGetSymbolAddress(&degp, g_deg);
    cudaMemsetAsync(degp, 0, NN * sizeof(int));

    // CSR build
    k_hist<<<(E + 1023) / 1024, 1024>>>(src, E);
    k_scanA<<<NB_SCAN, 1024>>>();
    k_scanC<<<NB_SCAN, 1024>>>(E);
    k_scatter<<<(EH + 1023) / 1024, 1024>>>(src, adj_vals, EH);

    // init embeddings + layer-0 reciprocal norms
    k_init<<<(NN + 7) / 8, 256>>>(user_emb, item_emb);

    // layers 0,1: full passes
    int ublocks = (N_USER + 7) / 8;
    int iblocks = (N_ITEM + 7) / 8;
    int ablocks = (NN + 7) / 8;
    for (int l = 0; l < 2; l++) {
        k_cos<<<ublocks, 256>>>(l & 1);
        k_rowsum_it<<<iblocks, 256>>>();
        k_spmm<<<ablocks, 256>>>(l & 1, W_prune, b_prune);
    }
    // layer 2: full cos + rowsum, then SpMM only at the 4096 sampled rows
    k_cos<<<ublocks, 256>>>(0);          // emb2 in g_embA
    k_rowsum_it<<<iblocks, 256>>>();
    int fblocks = (Bu + Bi + 7) / 8;
    k_final<<<fblocks, 256>>>(users, items, user_emb, item_emb,
                              W_prune, b_prune, Bu, Bi);

    // sigmoid GEMM on the pre-scaled sampled embeddings
    dim3 gblk(16, 16);
    dim3 ggrd((Bi + 63) / 64, (Bu + 63) / 64);
    k_gemm<<<ggrd, gblk>>>(out, Bu, Bi);
}

// round 11
// speedup vs baseline: 1.5391x; 1.0110x over previous
#include <cuda_runtime.h>
#include <math.h>

// Problem constants (fixed by the reference setup)
#define N_USER 60000
#define N_ITEM 40000
#define NN     (N_USER + N_ITEM)   // 100000 nodes
#define D      64
#define EMAX   800000
#define EHALF  (EMAX / 2)
#define NB_SCAN ((NN + 1023) / 1024)   // 98 blocks
#define INIT_BLKS ((NN + 7) / 8)       // 12500 (8 warps/block, warp per row)
#define HIST_BLKS 1024

// ---- static device scratch (no allocations allowed) ----
__device__ float  g_embA[NN * D];   // emb0 -> overwritten by emb2 (layer-1 output)
__device__ float  g_embB[NN * D];   // emb1 (layer-0 output), preserved
__device__ float  g_rnorm[NN];      // reciprocal norms
__device__ float  g_rowsum[NN];     // reciprocal L1 rowsums (1 if rowsum<=0)
__device__ float4 g_edge[EMAX];     // {col(bits), cos, mem, aval}
__device__ int2   g_cr[EHALF];      // user-side CSR slots: {col, reverse slot}
__device__ int    g_rowptr[NN + 1];
__device__ int    g_deg[NN];        // histogram, then scatter cursor (= rowptr start)
__device__ int    g_bsum[128];
__device__ float  g_U[2048 * D];    // 0.25*(emb0+..+emb3) at sampled user rows
__device__ float  g_I[2048 * D];    // same for items

// ---------------- fused: degree histogram + embedding init + rnorm0 ----------------

__global__ __launch_bounds__(256) void k_hist_init(const int* __restrict__ src, int E,
                                                   const float* __restrict__ ue,
                                                   const float* __restrict__ ie) {
    if (blockIdx.x < INIT_BLKS) {
        int row = blockIdx.x * 8 + (threadIdx.x >> 5);
        if (row >= NN) return;
        int lane = threadIdx.x & 31;
        const float* srcp = (row < N_USER) ? (ue + row * D) : (ie + (row - N_USER) * D);
        float2 v = *(const float2*)(srcp + lane * 2);
        *(float2*)(g_embA + row * D + lane * 2) = v;
        float s = v.x * v.x + v.y * v.y;
        #pragma unroll
        for (int o = 16; o; o >>= 1) s += __shfl_xor_sync(0xffffffffu, s, o);
        if (lane == 0) g_rnorm[row] = (s > 1e-24f) ? rsqrtf(s) : 0.f;
    } else {
        int base = (blockIdx.x - INIT_BLKS) * 256 + threadIdx.x;
        for (int e = base; e < E; e += HIST_BLKS * 256)
            atomicAdd(&g_deg[src[e]], 1);
    }
}

// ---------------- CSR build ----------------

__global__ void k_scanA() {
    __shared__ int wsum[32];
    int i = blockIdx.x * 1024 + threadIdx.x;
    int lane = threadIdx.x & 31, wid = threadIdx.x >> 5;
    int v = (i < NN) ? g_deg[i] : 0;
    int x = v;
    #pragma unroll
    for (int o = 1; o < 32; o <<= 1) {
        int y = __shfl_up_sync(0xffffffffu, x, o);
        if (lane >= o) x += y;
    }
    if (lane == 31) wsum[wid] = x;
    __syncthreads();
    if (wid == 0) {
        int s = wsum[lane];
        #pragma unroll
        for (int o = 1; o < 32; o <<= 1) {
            int y = __shfl_up_sync(0xffffffffu, s, o);
            if (lane >= o) s += y;
        }
        wsum[lane] = s;
    }
    __syncthreads();
    int woff = (wid > 0) ? wsum[wid - 1] : 0;
    int incl = x + woff;
    if (i < NN) g_rowptr[i] = incl - v;  // exclusive, local to block
    if (threadIdx.x == 1023) g_bsum[blockIdx.x] = incl;
}

// adds cross-block offsets; sets g_deg = rowptr start (direct scatter cursor)
__global__ void k_scanC(int E) {
    __shared__ int ssum[128];
    int t = threadIdx.x;
    if (t < 128) ssum[t] = (t < blockIdx.x) ? g_bsum[t] : 0;
    __syncthreads();
    if (t < 64) ssum[t] += ssum[t + 64];
    __syncthreads();
    if (t < 32) {
        int s = ssum[t] + ssum[t + 32];
        #pragma unroll
        for (int o = 16; o; o >>= 1) s += __shfl_down_sync(0xffffffffu, s, o);
        if (t == 0) ssum[0] = s;
    }
    __syncthreads();
    int off = ssum[0];
    int i = blockIdx.x * 1024 + t;
    if (i < NN) {
        int rp = g_rowptr[i] + off;
        g_rowptr[i] = rp;
        g_deg[i] = rp;   // cursor starts at row base: atomicAdd gives slot directly
    }
    if (i == 0) g_rowptr[NN] = E;
}

// scatter BOTH directions of each undirected edge; cursor-direct (no rowptr loads)
__global__ void k_scatter(const int* __restrict__ src, const float* __restrict__ adj,
                          int EH) {
    for (int e = blockIdx.x * blockDim.x + threadIdx.x; e < EH;
         e += gridDim.x * blockDim.x) {
        int u = src[e];
        int i = src[e + EH];
        float a = adj[e];
        int pos1 = atomicAdd(&g_deg[u], 1);
        int pos2 = atomicAdd(&g_deg[i], 1);
        g_edge[pos1] = make_float4(__int_as_float(i), 0.f, a, a);
        g_edge[pos2] = make_float4(__int_as_float(u), 0.f, a, a);
        g_cr[pos1]   = make_int2(i, pos2);   // user rows occupy slots [0, EH)
    }
}

// ---------------- per-layer edge passes (verified R7/R10 bodies) ----------------
// k_cos: USER rows only (cos symmetric; scatter to reverse slot too).
// Warp per row; 4 edge-groups of 8 lanes; lane sl covers dims [4sl,4sl+4) and
// [32+4sl,+4) so each LDG.128 covers exactly one 128B line of the row.

__global__ __launch_bounds__(256) void k_cos(int cur) {
    const float* __restrict__ emb = cur ? g_embB : g_embA;
    int row = blockIdx.x * 8 + (threadIdx.x >> 5);
    if (row >= N_USER) return;
    int lane = threadIdx.x & 31;
    int g = lane >> 3, sl = lane & 7;

    const float* rp = emb + row * D + sl * 4;
    float4 e0 = *(const float4*)(rp);
    float4 e1 = *(const float4*)(rp + 32);
    float rn_r = g_rnorm[row];

    int beg = g_rowptr[row], end = g_rowptr[row + 1];
    int nit = (end - beg + 3) >> 2;

    int pos = beg + g;
    bool actn = pos < end;
    int2 crn = actn ? g_cr[pos] : make_int2(0, 0);

    float rs = 0.f;
    for (int it = 0; it < nit; it++) {
        bool act = actn;
        int2 cr = crn;
        int curpos = pos;
        pos += 4;
        actn = pos < end;
        if (actn) crn = g_cr[pos];

        float p = 0.f;
        float rn_c = 0.f;
        if (act) {
            const float* cp = emb + cr.x * D + sl * 4;
            float4 d0 = *(const float4*)(cp);
            float4 d1 = *(const float4*)(cp + 32);
            rn_c = g_rnorm[cr.x];
            p = e0.x * d0.x + e0.y * d0.y + e0.z * d0.z + e0.w * d0.w
              + e1.x * d1.x + e1.y * d1.y + e1.z * d1.z + e1.w * d1.w;
        }
        p += __shfl_xor_sync(0xffffffffu, p, 1);
        p += __shfl_xor_sync(0xffffffffu, p, 2);
        p += __shfl_xor_sync(0xffffffffu, p, 4);
        float cs = p * rn_r * rn_c;
        if (act && sl == 0) {
            ((float*)(g_edge + curpos))[1] = cs;   // user-side slot
            ((float*)(g_edge + cr.y))[1]   = cs;   // item-side (reverse) slot
        }
        rs += fabsf(cs);
    }
    rs += __shfl_xor_sync(0xffffffffu, rs, 8);
    rs += __shfl_xor_sync(0xffffffffu, rs, 16);
    if (lane == 0) g_rowsum[row] = (rs > 0.f) ? 1.f / rs : 1.f;
}

// item-row reciprocal L1 rowsums from the already-written cos values
__global__ __launch_bounds__(256) void k_rowsum_it() {
    int row = N_USER + blockIdx.x * 8 + (threadIdx.x >> 5);
    if (row >= NN) return;
    int lane = threadIdx.x & 31;
    int beg = g_rowptr[row], end = g_rowptr[row + 1];
    float rs = 0.f;
    for (int pos = beg + lane; pos < end; pos += 32)
        rs += fabsf(((const float*)(g_edge + pos))[1]);
    #pragma unroll
    for (int o = 16; o; o >>= 1) rs += __shfl_xor_sync(0xffffffffu, rs, o);
    if (lane == 0) g_rowsum[row] = (rs > 0.f) ? 1.f / rs : 1.f;
}

// layers 0,1 only: coef -> prune -> mem EMA -> SpMM row accumulate (+ next rnorm)
__global__ __launch_bounds__(256) void k_spmm(int cur,
                                              const float* __restrict__ W,
                                              const float* __restrict__ B) {
    const float* __restrict__ embin = cur ? g_embB : g_embA;
    float* embout                   = cur ? g_embA : g_embB;
    int row = blockIdx.x * 8 + (threadIdx.x >> 5);
    if (row >= NN) return;
    int lane = threadIdx.x & 31;
    int g = lane >> 3, sl = lane & 7;

    float w0 = W[0], w1 = W[1], bb = B[0];
    float invr = g_rowsum[row];
    int beg = g_rowptr[row], end = g_rowptr[row + 1];
    int nit = (end - beg + 3) >> 2;

    int pos = beg + g;
    bool actn = pos < end;
    float4 en = actn ? g_edge[pos] : make_float4(0, 0, 0, 0);

    float a0 = 0.f, a1 = 0.f, a2 = 0.f, a3 = 0.f;
    float a4 = 0.f, a5 = 0.f, a6 = 0.f, a7 = 0.f;
    for (int it = 0; it < nit; it++) {
        bool act = actn;
        float4 er = en;
        int curpos = pos;
        pos += 4;
        actn = pos < end;
        if (actn) en = g_edge[pos];

        if (act) {
            int c = __float_as_int(er.x);
            float cs = er.y;
            float c1 = cs * invr;
            float c2 = cs * g_rowsum[c];           // cos symmetric
            float z = w0 * c1 + w1 * c2 + bb;      // sigmoid(z)>0.5 <=> z>0
            float coef = (z > 0.f) ? c1 : 0.f;
            float m = 0.5f * (er.z + coef);
            if (sl == 0) ((float*)(g_edge + curpos))[2] = m;
            float gv = m * er.w;
            const float* cp = embin + c * D + sl * 4;
            float4 d0 = *(const float4*)(cp);
            float4 d1 = *(const float4*)(cp + 32);
            a0 += gv * d0.x; a1 += gv * d0.y; a2 += gv * d0.z; a3 += gv * d0.w;
            a4 += gv * d1.x; a5 += gv * d1.y; a6 += gv * d1.z; a7 += gv * d1.w;
        }
    }
    #pragma unroll
    for (int o = 8; o <= 16; o <<= 1) {
        a0 += __shfl_xor_sync(0xffffffffu, a0, o);
        a1 += __shfl_xor_sync(0xffffffffu, a1, o);
        a2 += __shfl_xor_sync(0xffffffffu, a2, o);
        a3 += __shfl_xor_sync(0xffffffffu, a3, o);
        a4 += __shfl_xor_sync(0xffffffffu, a4, o);
        a5 += __shfl_xor_sync(0xffffffffu, a5, o);
        a6 += __shfl_xor_sync(0xffffffffu, a6, o);
        a7 += __shfl_xor_sync(0xffffffffu, a7, o);
    }
    float ss = a0 * a0 + a1 * a1 + a2 * a2 + a3 * a3
             + a4 * a4 + a5 * a5 + a6 * a6 + a7 * a7;
    ss += __shfl_xor_sync(0xffffffffu, ss, 1);
    ss += __shfl_xor_sync(0xffffffffu, ss, 2);
    ss += __shfl_xor_sync(0xffffffffu, ss, 4);
    if (g == 0) {
        float* op = embout + row * D + sl * 4;
        *(float4*)(op)      = make_float4(a0, a1, a2, a3);
        *(float4*)(op + 32) = make_float4(a4, a5, a6, a7);
        if (sl == 0) g_rnorm[row] = (ss > 1e-24f) ? rsqrtf(ss) : 0.f;
    }
}

// layer-2 SpMM restricted to the SAMPLED rows only, fused with the light mean:
// g_U/g_I = 0.25*(emb0(inputs) + emb1(embB) + emb2(embA) + emb3(computed here))
__global__ __launch_bounds__(256) void k_final(const int* __restrict__ users,
                                               const int* __restrict__ items,
                                               const float* __restrict__ ue,
                                               const float* __restrict__ ie,
                                               const float* __restrict__ W,
                                               const float* __restrict__ B,
                                               int Bu, int Bi) {
    int idx = blockIdx.x * 8 + (threadIdx.x >> 5);   // sample index
    if (idx >= Bu + Bi) return;
    int lane = threadIdx.x & 31;
    int g = lane >> 3, sl = lane & 7;

    bool isU = idx < Bu;
    int row = isU ? users[idx] : (N_USER + items[idx - Bu]);
    float* outp = isU ? (g_U + idx * D) : (g_I + (idx - Bu) * D);
    const float* e0p = isU ? (ue + row * D) : (ie + (row - N_USER) * D);

    const float* __restrict__ embin = g_embA;   // emb2 (layer-1 output)

    float w0 = W[0], w1 = W[1], bb = B[0];
    float invr = g_rowsum[row];
    int beg = g_rowptr[row], end = g_rowptr[row + 1];
    int nit = (end - beg + 3) >> 2;

    int pos = beg + g;
    bool actn = pos < end;
    float4 en = actn ? g_edge[pos] : make_float4(0, 0, 0, 0);

    float a0 = 0.f, a1 = 0.f, a2 = 0.f, a3 = 0.f;
    float a4 = 0.f, a5 = 0.f, a6 = 0.f, a7 = 0.f;
    for (int it = 0; it < nit; it++) {
        bool act = actn;
        float4 er = en;
        pos += 4;
        actn = pos < end;
        if (actn) en = g_edge[pos];

        if (act) {
            int c = __float_as_int(er.x);
            float cs = er.y;
            float c1 = cs * invr;
            float c2 = cs * g_rowsum[c];
            float z = w0 * c1 + w1 * c2 + bb;
            float coef = (z > 0.f) ? c1 : 0.f;
            float m = 0.5f * (er.z + coef);      // no mem writeback (last layer)
            float gv = m * er.w;
            const float* cp = embin + c * D + sl * 4;
            float4 d0 = *(const float4*)(cp);
            float4 d1 = *(const float4*)(cp + 32);
            a0 += gv * d0.x; a1 += gv * d0.y; a2 += gv * d0.z; a3 += gv * d0.w;
            a4 += gv * d1.x; a5 += gv * d1.y; a6 += gv * d1.z; a7 += gv * d1.w;
        }
    }
    #pragma unroll
    for (int o = 8; o <= 16; o <<= 1) {
        a0 += __shfl_xor_sync(0xffffffffu, a0, o);
        a1 += __shfl_xor_sync(0xffffffffu, a1, o);
        a2 += __shfl_xor_sync(0xffffffffu, a2, o);
        a3 += __shfl_xor_sync(0xffffffffu, a3, o);
        a4 += __shfl_xor_sync(0xffffffffu, a4, o);
        a5 += __shfl_xor_sync(0xffffffffu, a5, o);
        a6 += __shfl_xor_sync(0xffffffffu, a6, o);
        a7 += __shfl_xor_sync(0xffffffffu, a7, o);
    }
    if (g == 0) {
        float4 z0 = *(const float4*)(e0p + sl * 4);           // emb0 (inputs)
        float4 z1 = *(const float4*)(e0p + sl * 4 + 32);
        const float* b1 = g_embB + row * D + sl * 4;          // emb1
        float4 y0 = *(const float4*)(b1);
        float4 y1 = *(const float4*)(b1 + 32);
        const float* b2 = g_embA + row * D + sl * 4;          // emb2
        float4 x0 = *(const float4*)(b2);
        float4 x1 = *(const float4*)(b2 + 32);
        float4 r0 = make_float4(0.25f * (z0.x + y0.x + x0.x + a0),
                                0.25f * (z0.y + y0.y + x0.y + a1),
                                0.25f * (z0.z + y0.z + x0.z + a2),
                                0.25f * (z0.w + y0.w + x0.w + a3));
        float4 r1 = make_float4(0.25f * (z1.x + y1.x + x1.x + a4),
                                0.25f * (z1.y + y1.y + x1.y + a5),
                                0.25f * (z1.z + y1.z + x1.z + a6),
                                0.25f * (z1.w + y1.w + x1.w + a7));
        *(float4*)(outp + sl * 4)      = r0;
        *(float4*)(outp + sl * 4 + 32) = r1;
    }
}

// ---------------- final sigmoid GEMM (dense g_U x g_I^T; FMA-bound ~16us floor) ----

__global__ void k_gemm(float* __restrict__ out, int Bu, int Bi) {
    __shared__ float As[64][65];
    __shared__ float Bs[64][65];
    int tx = threadIdx.x, ty = threadIdx.y;       // 16x16
    int t = ty * 16 + tx;
    int rowBase = blockIdx.y * 64, colBase = blockIdx.x * 64;
    #pragma unroll
    for (int i = 0; i < 4; i++) {
        int j = t + i * 256;       // float4 slot 0..1023
        int r = j >> 4;
        int kq = (j & 15) * 4;
        float4 a = (rowBase + r < Bu) ? *(const float4*)(g_U + (rowBase + r) * 64 + kq)
                                      : make_float4(0, 0, 0, 0);
        As[r][kq] = a.x; As[r][kq + 1] = a.y; As[r][kq + 2] = a.z; As[r][kq + 3] = a.w;
        float4 b = (colBase + r < Bi) ? *(const float4*)(g_I + (colBase + r) * 64 + kq)
                                      : make_float4(0, 0, 0, 0);
        Bs[r][kq] = b.x; Bs[r][kq + 1] = b.y; Bs[r][kq + 2] = b.z; Bs[r][kq + 3] = b.w;
    }
    __syncthreads();
    float acc[4][4] = {};
    #pragma unroll
    for (int k = 0; k < 64; k++) {
        float a0 = As[ty * 4 + 0][k], a1 = As[ty * 4 + 1][k];
        float a2 = As[ty * 4 + 2][k], a3 = As[ty * 4 + 3][k];
        float b0 = Bs[tx * 4 + 0][k], b1 = Bs[tx * 4 + 1][k];
        float b2 = Bs[tx * 4 + 2][k], b3 = Bs[tx * 4 + 3][k];
        acc[0][0] += a0 * b0; acc[0][1] += a0 * b1; acc[0][2] += a0 * b2; acc[0][3] += a0 * b3;
        acc[1][0] += a1 * b0; acc[1][1] += a1 * b1; acc[1][2] += a1 * b2; acc[1][3] += a1 * b3;
        acc[2][0] += a2 * b0; acc[2][1] += a2 * b1; acc[2][2] += a2 * b2; acc[2][3] += a2 * b3;
        acc[3][0] += a3 * b0; acc[3][1] += a3 * b1; acc[3][2] += a3 * b2; acc[3][3] += a3 * b3;
    }
    #pragma unroll
    for (int i = 0; i < 4; i++)
        #pragma unroll
        for (int j = 0; j < 4; j++) {
            int r = rowBase + ty * 4 + i;
            int c = colBase + tx * 4 + j;
            if (r < Bu && c < Bi)
                out[r * Bi + c] = 1.f / (1.f + __expf(-acc[i][j]));
        }
}

// ---------------- launch ----------------

extern "C" void kernel_launch(void* const* d_in, const int* in_sizes, int n_in,
                              void* d_out, int out_size) {
    const int*   users    = (const int*)d_in[0];
    const int*   items    = (const int*)d_in[1];
    const float* user_emb = (const float*)d_in[2];
    const float* item_emb = (const float*)d_in[3];
    const float* W_prune  = (const float*)d_in[4];
    const float* b_prune  = (const float*)d_in[5];
    const int*   src      = (const int*)d_in[6];
    // d_in[7] = dst (mirrors src), d_in[8] = rev_perm (unused)
    const float* adj_vals = (const float*)d_in[9];

    int Bu = in_sizes[0];
    int Bi = in_sizes[1];
    int E  = in_sizes[6];
    int EH = E / 2;

    float* out = (float*)d_out;

    // zero degree counters
    void* degp = nullptr;
    cudaGetSymbolAddress(&degp, g_deg);
    cudaMemsetAsync(degp, 0, NN * sizeof(int));

    // fused: degree histogram + embedding init + layer-0 rnorm
    k_hist_init<<<INIT_BLKS + HIST_BLKS, 256>>>(src, E, user_emb, item_emb);

    // CSR build (scanC leaves g_deg = rowptr start for cursor-direct scatter)
    k_scanA<<<NB_SCAN, 1024>>>();
    k_scanC<<<NB_SCAN, 1024>>>(E);
    k_scatter<<<(EH + 1023) / 1024, 1024>>>(src, adj_vals, EH);

    // layers 0,1: full passes
    int ublocks = (N_USER + 7) / 8;
    int iblocks = (N_ITEM + 7) / 8;
    int ablocks = (NN + 7) / 8;
    for (int l = 0; l < 2; l++) {
        k_cos<<<ublocks, 256>>>(l & 1);
        k_rowsum_it<<<iblocks, 256>>>();
        k_spmm<<<ablocks, 256>>>(l & 1, W_prune, b_prune);
    }
    // layer 2: full cos + rowsum, then SpMM only at the 4096 sampled rows
    k_cos<<<ublocks, 256>>>(0);          // emb2 in g_embA
    k_rowsum_it<<<iblocks, 256>>>();
    int fblocks = (Bu + Bi + 7) / 8;
    k_final<<<fblocks, 256>>>(users, items, user_emb, item_emb,
                              W_prune, b_prune, Bu, Bi);

    // sigmoid GEMM on the pre-scaled sampled embeddings
    dim3 gblk(16, 16);
    dim3 ggrd((Bi + 63) / 64, (Bu + 63) / 64);
    k_gemm<<<ggrd, gblk>>>(out, Bu, Bi);
}

// round 12
// speedup vs baseline: 1.5550x; 1.0103x over previous
#include <cuda_runtime.h>
#include <math.h>

// Problem constants (fixed by the reference setup)
#define N_USER 60000
#define N_ITEM 40000
#define NN     (N_USER + N_ITEM)   // 100000 nodes
#define D      64
#define EMAX   800000
#define EHALF  (EMAX / 2)
#define NB_SCAN ((NN + 1023) / 1024)   // 98 blocks
#define INIT_BLKS ((NN + 7) / 8)       // 12500 (8 warps/block, warp per row)
#define HIST_BLKS 1024

// ---- static device scratch (no allocations allowed) ----
__device__ float  g_embA[NN * D];   // emb0 -> overwritten by emb2 (layer-1 output)
__device__ float  g_embB[NN * D];   // emb1 (layer-0 output), preserved
__device__ float  g_rnorm[NN];      // reciprocal norms
__device__ float  g_rowsum[NN];     // reciprocal L1 rowsums (1 if rowsum<=0)
__device__ float  g_rowacc[N_ITEM]; // item rowsum accumulators (atomic)
__device__ float4 g_edge[EMAX];     // {col(bits), cos, mem, aval}
__device__ int2   g_cr[EHALF];      // user-side CSR slots: {col, reverse slot}
__device__ int    g_rowptr[NN + 1];
__device__ int    g_deg[NN];        // histogram, then scatter cursor (= rowptr start)
__device__ int    g_bsum[128];
__device__ float  g_U[2048 * D];    // 0.25*(emb0+..+emb3) at sampled user rows
__device__ float  g_I[2048 * D];    // same for items

// ---------------- fused: degree histogram + embedding init + rnorm0 ----------------

__global__ __launch_bounds__(256) void k_hist_init(const int* __restrict__ src, int E,
                                                   const float* __restrict__ ue,
                                                   const float* __restrict__ ie) {
    if (blockIdx.x < INIT_BLKS) {
        int row = blockIdx.x * 8 + (threadIdx.x >> 5);
        if (row >= NN) return;
        int lane = threadIdx.x & 31;
        const float* srcp = (row < N_USER) ? (ue + row * D) : (ie + (row - N_USER) * D);
        float2 v = *(const float2*)(srcp + lane * 2);
        *(float2*)(g_embA + row * D + lane * 2) = v;
        float s = v.x * v.x + v.y * v.y;
        #pragma unroll
        for (int o = 16; o; o >>= 1) s += __shfl_xor_sync(0xffffffffu, s, o);
        if (lane == 0) g_rnorm[row] = (s > 1e-24f) ? rsqrtf(s) : 0.f;
    } else {
        int base = (blockIdx.x - INIT_BLKS) * 256 + threadIdx.x;
        for (int e = base; e < E; e += HIST_BLKS * 256)
            atomicAdd(&g_deg[src[e]], 1);
    }
}

// ---------------- CSR build ----------------

__global__ void k_scanA() {
    __shared__ int wsum[32];
    int i = blockIdx.x * 1024 + threadIdx.x;
    int lane = threadIdx.x & 31, wid = threadIdx.x >> 5;
    int v = (i < NN) ? g_deg[i] : 0;
    int x = v;
    #pragma unroll
    for (int o = 1; o < 32; o <<= 1) {
        int y = __shfl_up_sync(0xffffffffu, x, o);
        if (lane >= o) x += y;
    }
    if (lane == 31) wsum[wid] = x;
    __syncthreads();
    if (wid == 0) {
        int s = wsum[lane];
        #pragma unroll
        for (int o = 1; o < 32; o <<= 1) {
            int y = __shfl_up_sync(0xffffffffu, s, o);
            if (lane >= o) s += y;
        }
        wsum[lane] = s;
    }
    __syncthreads();
    int woff = (wid > 0) ? wsum[wid - 1] : 0;
    int incl = x + woff;
    if (i < NN) g_rowptr[i] = incl - v;  // exclusive, local to block
    if (threadIdx.x == 1023) g_bsum[blockIdx.x] = incl;
}

// adds cross-block offsets; sets g_deg = rowptr start (direct scatter cursor)
__global__ void k_scanC(int E) {
    __shared__ int ssum[128];
    int t = threadIdx.x;
    if (t < 128) ssum[t] = (t < blockIdx.x) ? g_bsum[t] : 0;
    __syncthreads();
    if (t < 64) ssum[t] += ssum[t + 64];
    __syncthreads();
    if (t < 32) {
        int s = ssum[t] + ssum[t + 32];
        #pragma unroll
        for (int o = 16; o; o >>= 1) s += __shfl_down_sync(0xffffffffu, s, o);
        if (t == 0) ssum[0] = s;
    }
    __syncthreads();
    int off = ssum[0];
    int i = blockIdx.x * 1024 + t;
    if (i < NN) {
        int rp = g_rowptr[i] + off;
        g_rowptr[i] = rp;
        g_deg[i] = rp;   // cursor starts at row base: atomicAdd gives slot directly
    }
    if (i == 0) g_rowptr[NN] = E;
}

// scatter BOTH directions; 4 edges/thread (MLP=4 on the atomic chains),
// vectorized int4/float4 input loads, cursor-direct slots.
__global__ __launch_bounds__(256) void k_scatter(const int* __restrict__ src,
                                                 const float* __restrict__ adj,
                                                 int EH) {
    int t = blockIdx.x * blockDim.x + threadIdx.x;
    int base = t * 4;
    if (base >= EH) return;

    int u[4], iv[4];
    float a[4];
    int n;
    if (base + 4 <= EH) {
        n = 4;
        int4 uu = *(const int4*)(src + base);
        u[0] = uu.x; u[1] = uu.y; u[2] = uu.z; u[3] = uu.w;
        int4 ii = *(const int4*)(src + base + EH);        // EH multiple of 4 in practice
        iv[0] = ii.x; iv[1] = ii.y; iv[2] = ii.z; iv[3] = ii.w;
        float4 aa = *(const float4*)(adj + base);
        a[0] = aa.x; a[1] = aa.y; a[2] = aa.z; a[3] = aa.w;
    } else {
        n = EH - base;
        for (int k = 0; k < n; k++) {
            u[k]  = src[base + k];
            iv[k] = src[base + k + EH];
            a[k]  = adj[base + k];
        }
    }
    int p1[4], p2[4];
    #pragma unroll
    for (int k = 0; k < 4; k++)
        if (k < n) {
            p1[k] = atomicAdd(&g_deg[u[k]], 1);
            p2[k] = atomicAdd(&g_deg[iv[k]], 1);
        }
    #pragma unroll
    for (int k = 0; k < 4; k++)
        if (k < n) {
            g_edge[p1[k]] = make_float4(__int_as_float(iv[k]), 0.f, a[k], a[k]);
            g_edge[p2[k]] = make_float4(__int_as_float(u[k]), 0.f, a[k], a[k]);
            g_cr[p1[k]]   = make_int2(iv[k], p2[k]);   // user rows occupy slots [0, EH)
        }
}

// ---------------- per-layer edge passes ----------------
// k_cos: USER rows only (cos symmetric; scatter to reverse slot too).
// Item rowsums accumulate via spread atomics (REDG) into g_rowacc.

__global__ __launch_bounds__(256) void k_cos(int cur) {
    const float* __restrict__ emb = cur ? g_embB : g_embA;
    int row = blockIdx.x * 8 + (threadIdx.x >> 5);
    if (row >= N_USER) return;
    int lane = threadIdx.x & 31;
    int g = lane >> 3, sl = lane & 7;

    const float* rp = emb + row * D + sl * 4;
    float4 e0 = *(const float4*)(rp);
    float4 e1 = *(const float4*)(rp + 32);
    float rn_r = g_rnorm[row];

    int beg = g_rowptr[row], end = g_rowptr[row + 1];
    int nit = (end - beg + 3) >> 2;

    int pos = beg + g;
    bool actn = pos < end;
    int2 crn = actn ? g_cr[pos] : make_int2(0, 0);

    float rs = 0.f;
    for (int it = 0; it < nit; it++) {
        bool act = actn;
        int2 cr = crn;
        int curpos = pos;
        pos += 4;
        actn = pos < end;
        if (actn) crn = g_cr[pos];

        float p = 0.f;
        float rn_c = 0.f;
        if (act) {
            const float* cp = emb + cr.x * D + sl * 4;
            float4 d0 = *(const float4*)(cp);
            float4 d1 = *(const float4*)(cp + 32);
            rn_c = g_rnorm[cr.x];
            p = e0.x * d0.x + e0.y * d0.y + e0.z * d0.z + e0.w * d0.w
              + e1.x * d1.x + e1.y * d1.y + e1.z * d1.z + e1.w * d1.w;
        }
        p += __shfl_xor_sync(0xffffffffu, p, 1);
        p += __shfl_xor_sync(0xffffffffu, p, 2);
        p += __shfl_xor_sync(0xffffffffu, p, 4);
        float cs = p * rn_r * rn_c;
        if (act && sl == 0) {
            ((float*)(g_edge + curpos))[1] = cs;   // user-side slot
            ((float*)(g_edge + cr.y))[1]   = cs;   // item-side (reverse) slot
            atomicAdd(&g_rowacc[cr.x - N_USER], fabsf(cs));  // item L1 rowsum
        }
        rs += fabsf(cs);
    }
    rs += __shfl_xor_sync(0xffffffffu, rs, 8);
    rs += __shfl_xor_sync(0xffffffffu, rs, 16);
    if (lane == 0) g_rowsum[row] = (rs > 0.f) ? 1.f / rs : 1.f;
}

// invert the atomically-accumulated item rowsums; reset accumulators for next layer
__global__ void k_rsinv_it() {
    int i = blockIdx.x * blockDim.x + threadIdx.x;
    if (i < N_ITEM) {
        float rs = g_rowacc[i];
        g_rowsum[N_USER + i] = (rs > 0.f) ? 1.f / rs : 1.f;
        g_rowacc[i] = 0.f;
    }
}

// layers 0,1 only: coef -> prune -> mem EMA -> SpMM row accumulate (+ next rnorm)
__global__ __launch_bounds__(256) void k_spmm(int cur,
                                              const float* __restrict__ W,
                                              const float* __restrict__ B) {
    const float* __restrict__ embin = cur ? g_embB : g_embA;
    float* embout                   = cur ? g_embA : g_embB;
    int row = blockIdx.x * 8 + (threadIdx.x >> 5);
    if (row >= NN) return;
    int lane = threadIdx.x & 31;
    int g = lane >> 3, sl = lane & 7;

    float w0 = W[0], w1 = W[1], bb = B[0];
    float invr = g_rowsum[row];
    int beg = g_rowptr[row], end = g_rowptr[row + 1];
    int nit = (end - beg + 3) >> 2;

    int pos = beg + g;
    bool actn = pos < end;
    float4 en = actn ? g_edge[pos] : make_float4(0, 0, 0, 0);

    float a0 = 0.f, a1 = 0.f, a2 = 0.f, a3 = 0.f;
    float a4 = 0.f, a5 = 0.f, a6 = 0.f, a7 = 0.f;
    for (int it = 0; it < nit; it++) {
        bool act = actn;
        float4 er = en;
        int curpos = pos;
        pos += 4;
        actn = pos < end;
        if (actn) en = g_edge[pos];

        if (act) {
            int c = __float_as_int(er.x);
            float cs = er.y;
            float c1 = cs * invr;
            float c2 = cs * g_rowsum[c];           // cos symmetric
            float z = w0 * c1 + w1 * c2 + bb;      // sigmoid(z)>0.5 <=> z>0
            float coef = (z > 0.f) ? c1 : 0.f;
            float m = 0.5f * (er.z + coef);
            if (sl == 0) ((float*)(g_edge + curpos))[2] = m;
            float gv = m * er.w;
            const float* cp = embin + c * D + sl * 4;
            float4 d0 = *(const float4*)(cp);
            float4 d1 = *(const float4*)(cp + 32);
            a0 += gv * d0.x; a1 += gv * d0.y; a2 += gv * d0.z; a3 += gv * d0.w;
            a4 += gv * d1.x; a5 += gv * d1.y; a6 += gv * d1.z; a7 += gv * d1.w;
        }
    }
    #pragma unroll
    for (int o = 8; o <= 16; o <<= 1) {
        a0 += __shfl_xor_sync(0xffffffffu, a0, o);
        a1 += __shfl_xor_sync(0xffffffffu, a1, o);
        a2 += __shfl_xor_sync(0xffffffffu, a2, o);
        a3 += __shfl_xor_sync(0xffffffffu, a3, o);
        a4 += __shfl_xor_sync(0xffffffffu, a4, o);
        a5 += __shfl_xor_sync(0xffffffffu, a5, o);
        a6 += __shfl_xor_sync(0xffffffffu, a6, o);
        a7 += __shfl_xor_sync(0xffffffffu, a7, o);
    }
    float ss = a0 * a0 + a1 * a1 + a2 * a2 + a3 * a3
             + a4 * a4 + a5 * a5 + a6 * a6 + a7 * a7;
    ss += __shfl_xor_sync(0xffffffffu, ss, 1);
    ss += __shfl_xor_sync(0xffffffffu, ss, 2);
    ss += __shfl_xor_sync(0xffffffffu, ss, 4);
    if (g == 0) {
        float* op = embout + row * D + sl * 4;
        *(float4*)(op)      = make_float4(a0, a1, a2, a3);
        *(float4*)(op + 32) = make_float4(a4, a5, a6, a7);
        if (sl == 0) g_rnorm[row] = (ss > 1e-24f) ? rsqrtf(ss) : 0.f;
    }
}

// layer-2 SpMM restricted to the SAMPLED rows only, fused with the light mean:
// g_U/g_I = 0.25*(emb0(inputs) + emb1(embB) + emb2(embA) + emb3(computed here))
__global__ __launch_bounds__(256) void k_final(const int* __restrict__ users,
                                               const int* __restrict__ items,
                                               const float* __restrict__ ue,
                                               const float* __restrict__ ie,
                                               const float* __restrict__ W,
                                               const float* __restrict__ B,
                                               int Bu, int Bi) {
    int idx = blockIdx.x * 8 + (threadIdx.x >> 5);   // sample index
    if (idx >= Bu + Bi) return;
    int lane = threadIdx.x & 31;
    int g = lane >> 3, sl = lane & 7;

    bool isU = idx < Bu;
    int row = isU ? users[idx] : (N_USER + items[idx - Bu]);
    float* outp = isU ? (g_U + idx * D) : (g_I + (idx - Bu) * D);
    const float* e0p = isU ? (ue + row * D) : (ie + (row - N_USER) * D);

    const float* __restrict__ embin = g_embA;   // emb2 (layer-1 output)

    float w0 = W[0], w1 = W[1], bb = B[0];
    float invr = g_rowsum[row];
    int beg = g_rowptr[row], end = g_rowptr[row + 1];
    int nit = (end - beg + 3) >> 2;

    int pos = beg + g;
    bool actn = pos < end;
    float4 en = actn ? g_edge[pos] : make_float4(0, 0, 0, 0);

    float a0 = 0.f, a1 = 0.f, a2 = 0.f, a3 = 0.f;
    float a4 = 0.f, a5 = 0.f, a6 = 0.f, a7 = 0.f;
    for (int it = 0; it < nit; it++) {
        bool act = actn;
        float4 er = en;
        pos += 4;
        actn = pos < end;
        if (actn) en = g_edge[pos];

        if (act) {
            int c = __float_as_int(er.x);
            float cs = er.y;
            float c1 = cs * invr;
            float c2 = cs * g_rowsum[c];
            float z = w0 * c1 + w1 * c2 + bb;
            float coef = (z > 0.f) ? c1 : 0.f;
            float m = 0.5f * (er.z + coef);      // no mem writeback (last layer)
            float gv = m * er.w;
            const float* cp = embin + c * D + sl * 4;
            float4 d0 = *(const float4*)(cp);
            float4 d1 = *(const float4*)(cp + 32);
            a0 += gv * d0.x; a1 += gv * d0.y; a2 += gv * d0.z; a3 += gv * d0.w;
            a4 += gv * d1.x; a5 += gv * d1.y; a6 += gv * d1.z; a7 += gv * d1.w;
        }
    }
    #pragma unroll
    for (int o = 8; o <= 16; o <<= 1) {
        a0 += __shfl_xor_sync(0xffffffffu, a0, o);
        a1 += __shfl_xor_sync(0xffffffffu, a1, o);
        a2 += __shfl_xor_sync(0xffffffffu, a2, o);
        a3 += __shfl_xor_sync(0xffffffffu, a3, o);
        a4 += __shfl_xor_sync(0xffffffffu, a4, o);
        a5 += __shfl_xor_sync(0xffffffffu, a5, o);
        a6 += __shfl_xor_sync(0xffffffffu, a6, o);
        a7 += __shfl_xor_sync(0xffffffffu, a7, o);
    }
    if (g == 0) {
        float4 z0 = *(const float4*)(e0p + sl * 4);           // emb0 (inputs)
        float4 z1 = *(const float4*)(e0p + sl * 4 + 32);
        const float* b1 = g_embB + row * D + sl * 4;          // emb1
        float4 y0 = *(const float4*)(b1);
        float4 y1 = *(const float4*)(b1 + 32);
        const float* b2 = g_embA + row * D + sl * 4;          // emb2
        float4 x0 = *(const float4*)(b2);
        float4 x1 = *(const float4*)(b2 + 32);
        float4 r0 = make_float4(0.25f * (z0.x + y0.x + x0.x + a0),
                                0.25f * (z0.y + y0.y + x0.y + a1),
                                0.25f * (z0.z + y0.z + x0.z + a2),
                                0.25f * (z0.w + y0.w + x0.w + a3));
        float4 r1 = make_float4(0.25f * (z1.x + y1.x + x1.x + a4),
                                0.25f * (z1.y + y1.y + x1.y + a5),
                                0.25f * (z1.z + y1.z + x1.z + a6),
                                0.25f * (z1.w + y1.w + x1.w + a7));
        *(float4*)(outp + sl * 4)      = r0;
        *(float4*)(outp + sl * 4 + 32) = r1;
    }
}

// ---------------- final sigmoid GEMM (dense g_U x g_I^T; FMA-bound ~16us floor) ----

__global__ void k_gemm(float* __restrict__ out, int Bu, int Bi) {
    __shared__ float As[64][65];
    __shared__ float Bs[64][65];
    int tx = threadIdx.x, ty = threadIdx.y;       // 16x16
    int t = ty * 16 + tx;
    int rowBase = blockIdx.y * 64, colBase = blockIdx.x * 64;
    #pragma unroll
    for (int i = 0; i < 4; i++) {
        int j = t + i * 256;       // float4 slot 0..1023
        int r = j >> 4;
        int kq = (j & 15) * 4;
        float4 a = (rowBase + r < Bu) ? *(const float4*)(g_U + (rowBase + r) * 64 + kq)
                                      : make_float4(0, 0, 0, 0);
        As[r][kq] = a.x; As[r][kq + 1] = a.y; As[r][kq + 2] = a.z; As[r][kq + 3] = a.w;
        float4 b = (colBase + r < Bi) ? *(const float4*)(g_I + (colBase + r) * 64 + kq)
                                      : make_float4(0, 0, 0, 0);
        Bs[r][kq] = b.x; Bs[r][kq + 1] = b.y; Bs[r][kq + 2] = b.z; Bs[r][kq + 3] = b.w;
    }
    __syncthreads();
    float acc[4][4] = {};
    #pragma unroll
    for (int k = 0; k < 64; k++) {
        float a0 = As[ty * 4 + 0][k], a1 = As[ty * 4 + 1][k];
        float a2 = As[ty * 4 + 2][k], a3 = As[ty * 4 + 3][k];
        float b0 = Bs[tx * 4 + 0][k], b1 = Bs[tx * 4 + 1][k];
        float b2 = Bs[tx * 4 + 2][k], b3 = Bs[tx * 4 + 3][k];
        acc[0][0] += a0 * b0; acc[0][1] += a0 * b1; acc[0][2] += a0 * b2; acc[0][3] += a0 * b3;
        acc[1][0] += a1 * b0; acc[1][1] += a1 * b1; acc[1][2] += a1 * b2; acc[1][3] += a1 * b3;
        acc[2][0] += a2 * b0; acc[2][1] += a2 * b1; acc[2][2] += a2 * b2; acc[2][3] += a2 * b3;
        acc[3][0] += a3 * b0; acc[3][1] += a3 * b1; acc[3][2] += a3 * b2; acc[3][3] += a3 * b3;
    }
    #pragma unroll
    for (int i = 0; i < 4; i++)
        #pragma unroll
        for (int j = 0; j < 4; j++) {
            int r = rowBase + ty * 4 + i;
            int c = colBase + tx * 4 + j;
            if (r < Bu && c < Bi)
                out[r * Bi + c] = 1.f / (1.f + __expf(-acc[i][j]));
        }
}

// ---------------- launch ----------------

extern "C" void kernel_launch(void* const* d_in, const int* in_sizes, int n_in,
                              void* d_out, int out_size) {
    const int*   users    = (const int*)d_in[0];
    const int*   items    = (const int*)d_in[1];
    const float* user_emb = (const float*)d_in[2];
    const float* item_emb = (const float*)d_in[3];
    const float* W_prune  = (const float*)d_in[4];
    const float* b_prune  = (const float*)d_in[5];
    const int*   src      = (const int*)d_in[6];
    // d_in[7] = dst (mirrors src), d_in[8] = rev_perm (unused)
    const float* adj_vals = (const float*)d_in[9];

    int Bu = in_sizes[0];
    int Bi = in_sizes[1];
    int E  = in_sizes[6];
    int EH = E / 2;

    float* out = (float*)d_out;

    // zero degree counters + item rowsum accumulators
    void* degp = nullptr;
    cudaGetSymbolAddress(&degp, g_deg);
    cudaMemsetAsync(degp, 0, NN * sizeof(int));
    void* accp = nullptr;
    cudaGetSymbolAddress(&accp, g_rowacc);
    cudaMemsetAsync(accp, 0, N_ITEM * sizeof(float));

    // fused: degree histogram + embedding init + layer-0 rnorm
    k_hist_init<<<INIT_BLKS + HIST_BLKS, 256>>>(src, E, user_emb, item_emb);

    // CSR build (scanC leaves g_deg = rowptr start for cursor-direct scatter)
    k_scanA<<<NB_SCAN, 1024>>>();
    k_scanC<<<NB_SCAN, 1024>>>(E);
    k_scatter<<<(EH / 4 + 255) / 256, 256>>>(src, adj_vals, EH);

    // layers 0,1: full passes
    int ublocks = (N_USER + 7) / 8;
    int ablocks = (NN + 7) / 8;
    int riblocks = (N_ITEM + 1023) / 1024;
    for (int l = 0; l < 2; l++) {
        k_cos<<<ublocks, 256>>>(l & 1);
        k_rsinv_it<<<riblocks, 1024>>>();
        k_spmm<<<ablocks, 256>>>(l & 1, W_prune, b_prune);
    }
    // layer 2: full cos + rowsum, then SpMM only at the 4096 sampled rows
    k_cos<<<ublocks, 256>>>(0);          // emb2 in g_embA
    k_rsinv_it<<<riblocks, 1024>>>();
    int fblocks = (Bu + Bi + 7) / 8;
    k_final<<<fblocks, 256>>>(users, items, user_emb, item_emb,
                              W_prune, b_prune, Bu, Bi);

    // sigmoid GEMM on the pre-scaled sampled embeddings
    dim3 gblk(16, 16);
    dim3 ggrd((Bi + 63) / 64, (Bu + 63) / 64);
    k_gemm<<<ggrd, gblk>>>(out, Bu, Bi);
}

// round 13
// speedup vs baseline: 1.5673x; 1.0079x over previous
#include <cuda_runtime.h>
#include <math.h>

// Problem constants (fixed by the reference setup)
#define N_USER 60000
#define N_ITEM 40000
#define NN     (N_USER + N_ITEM)   // 100000 nodes
#define D      64
#define EMAX   800000
#define EHALF  (EMAX / 2)
#define NB_SCAN ((NN + 1023) / 1024)   // 98 blocks
#define INIT_BLKS ((NN + 7) / 8)       // 12500 (8 warps/block, warp per row)
#define HIST_BLKS 1024

// ---- static device scratch (no allocations allowed) ----
__device__ float  g_embA[NN * D];   // emb0 -> overwritten by emb2 (layer-1 output)
__device__ float  g_embB[NN * D];   // emb1 (layer-0 output), preserved
__device__ float  g_rnorm[NN];      // reciprocal norms
__device__ float  g_rowsum[NN];     // reciprocal L1 rowsums (1 if rowsum<=0)
__device__ float  g_rowacc[N_ITEM]; // item rowsum accumulators (atomic)
__device__ float4 g_edge[EMAX];     // {col(bits), cos, mem, aval}
__device__ int2   g_cr[EHALF];      // user-side CSR slots: {col, reverse slot}
__device__ int    g_off[EMAX];      // per-edge within-row offset (from hist atomics)
__device__ int    g_rowptr[NN + 1];
__device__ int    g_deg[NN];
__device__ int    g_bsum[128];
__device__ float  g_U[2048 * D];    // 0.25*(emb0+..+emb3) at sampled user rows
__device__ float  g_I[2048 * D];    // same for items

// ---------------- fused: degree histogram (+offset capture) + emb init + rnorm0 ----

__global__ __launch_bounds__(256) void k_hist_init(const int* __restrict__ src, int E,
                                                   const float* __restrict__ ue,
                                                   const float* __restrict__ ie) {
    if (blockIdx.x < INIT_BLKS) {
        int row = blockIdx.x * 8 + (threadIdx.x >> 5);
        if (row >= NN) return;
        int lane = threadIdx.x & 31;
        const float* srcp = (row < N_USER) ? (ue + row * D) : (ie + (row - N_USER) * D);
        float2 v = *(const float2*)(srcp + lane * 2);
        *(float2*)(g_embA + row * D + lane * 2) = v;
        float s = v.x * v.x + v.y * v.y;
        #pragma unroll
        for (int o = 16; o; o >>= 1) s += __shfl_xor_sync(0xffffffffu, s, o);
        if (lane == 0) g_rnorm[row] = (s > 1e-24f) ? rsqrtf(s) : 0.f;
    } else {
        // histogram that also records each edge's within-row slot offset
        int base = (blockIdx.x - INIT_BLKS) * 256 + threadIdx.x;
        for (int e = base; e < E; e += HIST_BLKS * 256)
            g_off[e] = atomicAdd(&g_deg[src[e]], 1);
    }
}

// ---------------- CSR build ----------------

__global__ void k_scanA() {
    __shared__ int wsum[32];
    int i = blockIdx.x * 1024 + threadIdx.x;
    int lane = threadIdx.x & 31, wid = threadIdx.x >> 5;
    int v = (i < NN) ? g_deg[i] : 0;
    int x = v;
    #pragma unroll
    for (int o = 1; o < 32; o <<= 1) {
        int y = __shfl_up_sync(0xffffffffu, x, o);
        if (lane >= o) x += y;
    }
    if (lane == 31) wsum[wid] = x;
    __syncthreads();
    if (wid == 0) {
        int s = wsum[lane];
        #pragma unroll
        for (int o = 1; o < 32; o <<= 1) {
            int y = __shfl_up_sync(0xffffffffu, s, o);
            if (lane >= o) s += y;
        }
        wsum[lane] = s;
    }
    __syncthreads();
    int woff = (wid > 0) ? wsum[wid - 1] : 0;
    int incl = x + woff;
    if (i < NN) g_rowptr[i] = incl - v;  // exclusive, local to block
    if (threadIdx.x == 1023) g_bsum[blockIdx.x] = incl;
}

// adds cross-block offsets
__global__ void k_scanC(int E) {
    __shared__ int ssum[128];
    int t = threadIdx.x;
    if (t < 128) ssum[t] = (t < blockIdx.x) ? g_bsum[t] : 0;
    __syncthreads();
    if (t < 64) ssum[t] += ssum[t + 64];
    __syncthreads();
    if (t < 32) {
        int s = ssum[t] + ssum[t + 32];
        #pragma unroll
        for (int o = 16; o; o >>= 1) s += __shfl_down_sync(0xffffffffu, s, o);
        if (t == 0) ssum[0] = s;
    }
    __syncthreads();
    int off = ssum[0];
    int i = blockIdx.x * 1024 + t;
    if (i < NN) g_rowptr[i] += off;
    if (i == 0) g_rowptr[NN] = E;
}

// atomic-free scatter: slot = rowptr[node] + precomputed offset
__global__ __launch_bounds__(1024) void k_scatter(const int* __restrict__ src,
                                                  const float* __restrict__ adj,
                                                  int EH) {
    int e = blockIdx.x * 1024 + threadIdx.x;
    if (e >= EH) return;
    int u  = src[e];
    int iv = src[e + EH];
    float a = adj[e];
    int pos1 = g_rowptr[u]  + g_off[e];
    int pos2 = g_rowptr[iv] + g_off[e + EH];
    g_edge[pos1] = make_float4(__int_as_float(iv), 0.f, a, a);
    g_edge[pos2] = make_float4(__int_as_float(u), 0.f, a, a);
    g_cr[pos1]   = make_int2(iv, pos2);   // user rows occupy slots [0, EH)
}

// ---------------- per-layer edge passes (verified bodies) ----------------
// k_cos: USER rows only (cos symmetric; scatter to reverse slot too).
// Item rowsums accumulate via spread atomics (REDG) into g_rowacc.

__global__ __launch_bounds__(256) void k_cos(int cur) {
    const float* __restrict__ emb = cur ? g_embB : g_embA;
    int row = blockIdx.x * 8 + (threadIdx.x >> 5);
    if (row >= N_USER) return;
    int lane = threadIdx.x & 31;
    int g = lane >> 3, sl = lane & 7;

    const float* rp = emb + row * D + sl * 4;
    float4 e0 = *(const float4*)(rp);
    float4 e1 = *(const float4*)(rp + 32);
    float rn_r = g_rnorm[row];

    int beg = g_rowptr[row], end = g_rowptr[row + 1];
    int nit = (end - beg + 3) >> 2;

    int pos = beg + g;
    bool actn = pos < end;
    int2 crn = actn ? g_cr[pos] : make_int2(0, 0);

    float rs = 0.f;
    for (int it = 0; it < nit; it++) {
        bool act = actn;
        int2 cr = crn;
        int curpos = pos;
        pos += 4;
        actn = pos < end;
        if (actn) crn = g_cr[pos];

        float p = 0.f;
        float rn_c = 0.f;
        if (act) {
            const float* cp = emb + cr.x * D + sl * 4;
            float4 d0 = *(const float4*)(cp);
            float4 d1 = *(const float4*)(cp + 32);
            rn_c = g_rnorm[cr.x];
            p = e0.x * d0.x + e0.y * d0.y + e0.z * d0.z + e0.w * d0.w
              + e1.x * d1.x + e1.y * d1.y + e1.z * d1.z + e1.w * d1.w;
        }
        p += __shfl_xor_sync(0xffffffffu, p, 1);
        p += __shfl_xor_sync(0xffffffffu, p, 2);
        p += __shfl_xor_sync(0xffffffffu, p, 4);
        float cs = p * rn_r * rn_c;
        if (act && sl == 0) {
            ((float*)(g_edge + curpos))[1] = cs;   // user-side slot
            ((float*)(g_edge + cr.y))[1]   = cs;   // item-side (reverse) slot
            atomicAdd(&g_rowacc[cr.x - N_USER], fabsf(cs));  // item L1 rowsum
        }
        rs += fabsf(cs);
    }
    rs += __shfl_xor_sync(0xffffffffu, rs, 8);
    rs += __shfl_xor_sync(0xffffffffu, rs, 16);
    if (lane == 0) g_rowsum[row] = (rs > 0.f) ? 1.f / rs : 1.f;
}

// invert the atomically-accumulated item rowsums; reset accumulators for next layer
__global__ void k_rsinv_it() {
    int i = blockIdx.x * blockDim.x + threadIdx.x;
    if (i < N_ITEM) {
        float rs = g_rowacc[i];
        g_rowsum[N_USER + i] = (rs > 0.f) ? 1.f / rs : 1.f;
        g_rowacc[i] = 0.f;
    }
}

// layers 0,1 only: coef -> prune -> mem EMA -> SpMM row accumulate (+ next rnorm)
__global__ __launch_bounds__(256) void k_spmm(int cur,
                                              const float* __restrict__ W,
                                              const float* __restrict__ B) {
    const float* __restrict__ embin = cur ? g_embB : g_embA;
    float* embout                   = cur ? g_embA : g_embB;
    int row = blockIdx.x * 8 + (threadIdx.x >> 5);
    if (row >= NN) return;
    int lane = threadIdx.x & 31;
    int g = lane >> 3, sl = lane & 7;

    float w0 = W[0], w1 = W[1], bb = B[0];
    float invr = g_rowsum[row];
    int beg = g_rowptr[row], end = g_rowptr[row + 1];
    int nit = (end - beg + 3) >> 2;

    int pos = beg + g;
    bool actn = pos < end;
    float4 en = actn ? g_edge[pos] : make_float4(0, 0, 0, 0);

    float a0 = 0.f, a1 = 0.f, a2 = 0.f, a3 = 0.f;
    float a4 = 0.f, a5 = 0.f, a6 = 0.f, a7 = 0.f;
    for (int it = 0; it < nit; it++) {
        bool act = actn;
        float4 er = en;
        int curpos = pos;
        pos += 4;
        actn = pos < end;
        if (actn) en = g_edge[pos];

        if (act) {
            int c = __float_as_int(er.x);
            float cs = er.y;
            float c1 = cs * invr;
            float c2 = cs * g_rowsum[c];           // cos symmetric
            float z = w0 * c1 + w1 * c2 + bb;      // sigmoid(z)>0.5 <=> z>0
            float coef = (z > 0.f) ? c1 : 0.f;
            float m = 0.5f * (er.z + coef);
            if (sl == 0) ((float*)(g_edge + curpos))[2] = m;
            float gv = m * er.w;
            const float* cp = embin + c * D + sl * 4;
            float4 d0 = *(const float4*)(cp);
            float4 d1 = *(const float4*)(cp + 32);
            a0 += gv * d0.x; a1 += gv * d0.y; a2 += gv * d0.z; a3 += gv * d0.w;
            a4 += gv * d1.x; a5 += gv * d1.y; a6 += gv * d1.z; a7 += gv * d1.w;
        }
    }
    #pragma unroll
    for (int o = 8; o <= 16; o <<= 1) {
        a0 += __shfl_xor_sync(0xffffffffu, a0, o);
        a1 += __shfl_xor_sync(0xffffffffu, a1, o);
        a2 += __shfl_xor_sync(0xffffffffu, a2, o);
        a3 += __shfl_xor_sync(0xffffffffu, a3, o);
        a4 += __shfl_xor_sync(0xffffffffu, a4, o);
        a5 += __shfl_xor_sync(0xffffffffu, a5, o);
        a6 += __shfl_xor_sync(0xffffffffu, a6, o);
        a7 += __shfl_xor_sync(0xffffffffu, a7, o);
    }
    float ss = a0 * a0 + a1 * a1 + a2 * a2 + a3 * a3
             + a4 * a4 + a5 * a5 + a6 * a6 + a7 * a7;
    ss += __shfl_xor_sync(0xffffffffu, ss, 1);
    ss += __shfl_xor_sync(0xffffffffu, ss, 2);
    ss += __shfl_xor_sync(0xffffffffu, ss, 4);
    if (g == 0) {
        float* op = embout + row * D + sl * 4;
        *(float4*)(op)      = make_float4(a0, a1, a2, a3);
        *(float4*)(op + 32) = make_float4(a4, a5, a6, a7);
        if (sl == 0) g_rnorm[row] = (ss > 1e-24f) ? rsqrtf(ss) : 0.f;
    }
}

// layer-2 SpMM restricted to the SAMPLED rows only, fused with the light mean:
// g_U/g_I = 0.25*(emb0(inputs) + emb1(embB) + emb2(embA) + emb3(computed here))
__global__ __launch_bounds__(256) void k_final(const int* __restrict__ users,
                                               const int* __restrict__ items,
                                               const float* __restrict__ ue,
                                               const float* __restrict__ ie,
                                               const float* __restrict__ W,
                                               const float* __restrict__ B,
                                               int Bu, int Bi) {
    int idx = blockIdx.x * 8 + (threadIdx.x >> 5);   // sample index
    if (idx >= Bu + Bi) return;
    int lane = threadIdx.x & 31;
    int g = lane >> 3, sl = lane & 7;

    bool isU = idx < Bu;
    int row = isU ? users[idx] : (N_USER + items[idx - Bu]);
    float* outp = isU ? (g_U + idx * D) : (g_I + (idx - Bu) * D);
    const float* e0p = isU ? (ue + row * D) : (ie + (row - N_USER) * D);

    const float* __restrict__ embin = g_embA;   // emb2 (layer-1 output)

    float w0 = W[0], w1 = W[1], bb = B[0];
    float invr = g_rowsum[row];
    int beg = g_rowptr[row], end = g_rowptr[row + 1];
    int nit = (end - beg + 3) >> 2;

    int pos = beg + g;
    bool actn = pos < end;
    float4 en = actn ? g_edge[pos] : make_float4(0, 0, 0, 0);

    float a0 = 0.f, a1 = 0.f, a2 = 0.f, a3 = 0.f;
    float a4 = 0.f, a5 = 0.f, a6 = 0.f, a7 = 0.f;
    for (int it = 0; it < nit; it++) {
        bool act = actn;
        float4 er = en;
        pos += 4;
        actn = pos < end;
        if (actn) en = g_edge[pos];

        if (act) {
            int c = __float_as_int(er.x);
            float cs = er.y;
            float c1 = cs * invr;
            float c2 = cs * g_rowsum[c];
            float z = w0 * c1 + w1 * c2 + bb;
            float coef = (z > 0.f) ? c1 : 0.f;
            float m = 0.5f * (er.z + coef);      // no mem writeback (last layer)
            float gv = m * er.w;
            const float* cp = embin + c * D + sl * 4;
            float4 d0 = *(const float4*)(cp);
            float4 d1 = *(const float4*)(cp + 32);
            a0 += gv * d0.x; a1 += gv * d0.y; a2 += gv * d0.z; a3 += gv * d0.w;
            a4 += gv * d1.x; a5 += gv * d1.y; a6 += gv * d1.z; a7 += gv * d1.w;
        }
    }
    #pragma unroll
    for (int o = 8; o <= 16; o <<= 1) {
        a0 += __shfl_xor_sync(0xffffffffu, a0, o);
        a1 += __shfl_xor_sync(0xffffffffu, a1, o);
        a2 += __shfl_xor_sync(0xffffffffu, a2, o);
        a3 += __shfl_xor_sync(0xffffffffu, a3, o);
        a4 += __shfl_xor_sync(0xffffffffu, a4, o);
        a5 += __shfl_xor_sync(0xffffffffu, a5, o);
        a6 += __shfl_xor_sync(0xffffffffu, a6, o);
        a7 += __shfl_xor_sync(0xffffffffu, a7, o);
    }
    if (g == 0) {
        float4 z0 = *(const float4*)(e0p + sl * 4);           // emb0 (inputs)
        float4 z1 = *(const float4*)(e0p + sl * 4 + 32);
        const float* b1 = g_embB + row * D + sl * 4;          // emb1
        float4 y0 = *(const float4*)(b1);
        float4 y1 = *(const float4*)(b1 + 32);
        const float* b2 = g_embA + row * D + sl * 4;          // emb2
        float4 x0 = *(const float4*)(b2);
        float4 x1 = *(const float4*)(b2 + 32);
        float4 r0 = make_float4(0.25f * (z0.x + y0.x + x0.x + a0),
                                0.25f * (z0.y + y0.y + x0.y + a1),
                                0.25f * (z0.z + y0.z + x0.z + a2),
                                0.25f * (z0.w + y0.w + x0.w + a3));
        float4 r1 = make_float4(0.25f * (z1.x + y1.x + x1.x + a4),
                                0.25f * (z1.y + y1.y + x1.y + a5),
                                0.25f * (z1.z + y1.z + x1.z + a6),
                                0.25f * (z1.w + y1.w + x1.w + a7));
        *(float4*)(outp + sl * 4)      = r0;
        *(float4*)(outp + sl * 4 + 32) = r1;
    }
}

// ---------------- final sigmoid GEMM (dense g_U x g_I^T; FMA-bound ~16us floor) ----

__global__ void k_gemm(float* __restrict__ out, int Bu, int Bi) {
    __shared__ float As[64][65];
    __shared__ float Bs[64][65];
    int tx = threadIdx.x, ty = threadIdx.y;       // 16x16
    int t = ty * 16 + tx;
    int rowBase = blockIdx.y * 64, colBase = blockIdx.x * 64;
    #pragma unroll
    for (int i = 0; i < 4; i++) {
        int j = t + i * 256;       // float4 slot 0..1023
        int r = j >> 4;
        int kq = (j & 15) * 4;
        float4 a = (rowBase + r < Bu) ? *(const float4*)(g_U + (rowBase + r) * 64 + kq)
                                      : make_float4(0, 0, 0, 0);
        As[r][kq] = a.x; As[r][kq + 1] = a.y; As[r][kq + 2] = a.z; As[r][kq + 3] = a.w;
        float4 b = (colBase + r < Bi) ? *(const float4*)(g_I + (colBase + r) * 64 + kq)
                                      : make_float4(0, 0, 0, 0);
        Bs[r][kq] = b.x; Bs[r][kq + 1] = b.y; Bs[r][kq + 2] = b.z; Bs[r][kq + 3] = b.w;
    }
    __syncthreads();
    float acc[4][4] = {};
    #pragma unroll
    for (int k = 0; k < 64; k++) {
        float a0 = As[ty * 4 + 0][k], a1 = As[ty * 4 + 1][k];
        float a2 = As[ty * 4 + 2][k], a3 = As[ty * 4 + 3][k];
        float b0 = Bs[tx * 4 + 0][k], b1 = Bs[tx * 4 + 1][k];
        float b2 = Bs[tx * 4 + 2][k], b3 = Bs[tx * 4 + 3][k];
        acc[0][0] += a0 * b0; acc[0][1] += a0 * b1; acc[0][2] += a0 * b2; acc[0][3] += a0 * b3;
        acc[1][0] += a1 * b0; acc[1][1] += a1 * b1; acc[1][2] += a1 * b2; acc[1][3] += a1 * b3;
        acc[2][0] += a2 * b0; acc[2][1] += a2 * b1; acc[2][2] += a2 * b2; acc[2][3] += a2 * b3;
        acc[3][0] += a3 * b0; acc[3][1] += a3 * b1; acc[3][2] += a3 * b2; acc[3][3] += a3 * b3;
    }
    #pragma unroll
    for (int i = 0; i < 4; i++)
        #pragma unroll
        for (int j = 0; j < 4; j++) {
            int r = rowBase + ty * 4 + i;
            int c = colBase + tx * 4 + j;
            if (r < Bu && c < Bi)
                out[r * Bi + c] = 1.f / (1.f + __expf(-acc[i][j]));
        }
}

// ---------------- launch ----------------

extern "C" void kernel_launch(void* const* d_in, const int* in_sizes, int n_in,
                              void* d_out, int out_size) {
    const int*   users    = (const int*)d_in[0];
    const int*   items    = (const int*)d_in[1];
    const float* user_emb = (const float*)d_in[2];
    const float* item_emb = (const float*)d_in[3];
    const float* W_prune  = (const float*)d_in[4];
    const float* b_prune  = (const float*)d_in[5];
    const int*   src      = (const int*)d_in[6];
    // d_in[7] = dst (mirrors src), d_in[8] = rev_perm (unused)
    const float* adj_vals = (const float*)d_in[9];

    int Bu = in_sizes[0];
    int Bi = in_sizes[1];
    int E  = in_sizes[6];
    int EH = E / 2;

    float* out = (float*)d_out;

    // zero degree counters + item rowsum accumulators
    void* degp = nullptr;
    cudaGetSymbolAddress(&degp, g_deg);
    cudaMemsetAsync(degp, 0, NN * sizeof(int));
    void* accp = nullptr;
    cudaGetSymbolAddress(&accp, g_rowacc);
    cudaMemsetAsync(accp, 0, N_ITEM * sizeof(float));

    // fused: degree histogram (capturing per-edge offsets) + emb init + rnorm0
    k_hist_init<<<INIT_BLKS + HIST_BLKS, 256>>>(src, E, user_emb, item_emb);

    // CSR build; scatter is atomic-free (rowptr + captured offset)
    k_scanA<<<NB_SCAN, 1024>>>();
    k_scanC<<<NB_SCAN, 1024>>>(E);
    k_scatter<<<(EH + 1023) / 1024, 1024>>>(src, adj_vals, EH);

    // layers 0,1: full passes
    int ublocks = (N_USER + 7) / 8;
    int ablocks = (NN + 7) / 8;
    int riblocks = (N_ITEM + 1023) / 1024;
    for (int l = 0; l < 2; l++) {
        k_cos<<<ublocks, 256>>>(l & 1);
        k_rsinv_it<<<riblocks, 1024>>>();
        k_spmm<<<ablocks, 256>>>(l & 1, W_prune, b_prune);
    }
    // layer 2: full cos + rowsum, then SpMM only at the 4096 sampled rows
    k_cos<<<ublocks, 256>>>(0);          // emb2 in g_embA
    k_rsinv_it<<<riblocks, 1024>>>();
    int fblocks = (Bu + Bi + 7) / 8;
    k_final<<<fblocks, 256>>>(users, items, user_emb, item_emb,
                              W_prune, b_prune, Bu, Bi);

    // sigmoid GEMM on the pre-scaled sampled embeddings
    dim3 gblk(16, 16);
    dim3 ggrd((Bi + 63) / 64, (Bu + 63) / 64);
    k_gemm<<<ggrd, gblk>>>(out, Bu, Bi);
}